// round 1
// baseline (speedup 1.0000x reference)
#include <cuda_runtime.h>
#include <math.h>

#define BATCH  4
#define SEQ    1024
#define DMODEL 512
#define DINNER 1024
#define DSTATE 32
#define DTRANK 32
#define DBC_W  96
#define NROWS  (BATCH*SEQ)   // 4096

// ---------------- scratch (static device globals; no allocation) ----------------
__device__ float g_xperm [BATCH*SEQ*DMODEL];     // permuted tokens (residual too)
__device__ float g_xz    [BATCH*SEQ*2*DINNER];   // in_proj output [bt, 2048]
__device__ float g_ut    [BATCH*DINNER*SEQ];     // silu(conv(xm)) transposed [b,d,t]
__device__ float g_zt    [BATCH*DINNER*SEQ];     // silu(z) transposed [b,d,t]
__device__ float g_dbc   [BATCH*SEQ*DBC_W];      // x_proj output [bt, 96]
__device__ float g_deltat[BATCH*DINNER*SEQ];     // softplus(dt@W+b) transposed [b,d,t]
__device__ float g_yt    [BATCH*DINNER*SEQ];     // scan output [b,d,t]
__device__ float g_y2    [BATCH*SEQ*DMODEL];     // out_proj output [bt, 512]
__device__ float g_yn    [BATCH*SEQ*DMODEL];     // layernorm output
__device__ float g_lin   [BATCH*SEQ*DMODEL];     // lin gemm output

__device__ __forceinline__ int perm_src(int p) {
  int r = p >> 5, c = p & 31;
  if (r & 1) c = 31 - c;
  return (r << 5) | c;
}

__device__ __forceinline__ float softplusf(float x) {
  return fmaxf(x, 0.f) + log1pf(expf(-fabsf(x)));
}
__device__ __forceinline__ float siluf(float x) {
  return x / (1.f + expf(-x));
}

// ---------------- permutation gather ----------------
__global__ void permute_kernel(const float* __restrict__ tokens) {
  int e = blockIdx.x * 256 + threadIdx.x;        // 0 .. 4096*512
  int c  = e & (DMODEL - 1);
  int bp = e >> 9;
  int b  = bp >> 10, p = bp & (SEQ - 1);
  int src = perm_src(p);
  g_xperm[e] = tokens[(b*SEQ + src)*DMODEL + c];
}

// ---------------- SGEMM, C[M,N] = A[M,K] * B[N,K]^T (both row-major) ----------------
__global__ void sgemm_nt(const float* __restrict__ A, const float* __restrict__ B,
                         float* __restrict__ C, int M, int N, int K) {
  __shared__ float As[16][64];
  __shared__ float Bs[16][64];
  int tid = threadIdx.x;
  int tx = tid & 15, ty = tid >> 4;
  int m0 = blockIdx.y * 64, n0 = blockIdx.x * 64;
  int lm = tid >> 2, lq = tid & 3;
  float acc[4][4] = {};
  for (int k0 = 0; k0 < K; k0 += 16) {
    float4 av = *(const float4*)&A[(size_t)(m0 + lm)*K + k0 + lq*4];
    float4 bv = *(const float4*)&B[(size_t)(n0 + lm)*K + k0 + lq*4];
    As[lq*4+0][lm] = av.x; As[lq*4+1][lm] = av.y; As[lq*4+2][lm] = av.z; As[lq*4+3][lm] = av.w;
    Bs[lq*4+0][lm] = bv.x; Bs[lq*4+1][lm] = bv.y; Bs[lq*4+2][lm] = bv.z; Bs[lq*4+3][lm] = bv.w;
    __syncthreads();
#pragma unroll
    for (int k = 0; k < 16; k++) {
      float4 a = *(const float4*)&As[k][ty*4];
      float4 bq = *(const float4*)&Bs[k][tx*4];
      float aa[4] = {a.x, a.y, a.z, a.w};
      float bb[4] = {bq.x, bq.y, bq.z, bq.w};
#pragma unroll
      for (int i = 0; i < 4; i++)
#pragma unroll
        for (int j = 0; j < 4; j++)
          acc[i][j] = fmaf(aa[i], bb[j], acc[i][j]);
    }
    __syncthreads();
  }
#pragma unroll
  for (int i = 0; i < 4; i++)
#pragma unroll
    for (int j = 0; j < 4; j++)
      C[(size_t)(m0 + ty*4 + i)*N + n0 + tx*4 + j] = acc[i][j];
}

// ---------------- SGEMM with A transposed: C[M,N] = At^T * B^T ----------------
// At is [K, M] (ld = M); B is [N, K]; batched via blockIdx.z
__global__ void sgemm_tn(const float* __restrict__ At, const float* __restrict__ B,
                         float* __restrict__ C, int M, int N, int K,
                         int strideA, int strideC) {
  At += (size_t)blockIdx.z * strideA;
  C  += (size_t)blockIdx.z * strideC;
  __shared__ float As[16][64];
  __shared__ float Bs[16][64];
  int tid = threadIdx.x;
  int tx = tid & 15, ty = tid >> 4;
  int m0 = blockIdx.y * 64, n0 = blockIdx.x * 64;
  int lk = tid >> 4, lm4 = (tid & 15) * 4;     // As loader
  int ln = tid >> 2, lq = tid & 3;             // Bs loader
  float acc[4][4] = {};
  for (int k0 = 0; k0 < K; k0 += 16) {
    float4 av = *(const float4*)&At[(size_t)(k0 + lk)*M + m0 + lm4];
    *(float4*)&As[lk][lm4] = av;
    float4 bv = make_float4(0.f, 0.f, 0.f, 0.f);
    if (n0 + ln < N) bv = *(const float4*)&B[(size_t)(n0 + ln)*K + k0 + lq*4];
    Bs[lq*4+0][ln] = bv.x; Bs[lq*4+1][ln] = bv.y; Bs[lq*4+2][ln] = bv.z; Bs[lq*4+3][ln] = bv.w;
    __syncthreads();
#pragma unroll
    for (int k = 0; k < 16; k++) {
      float4 a = *(const float4*)&As[k][ty*4];
      float4 bq = *(const float4*)&Bs[k][tx*4];
      float aa[4] = {a.x, a.y, a.z, a.w};
      float bb[4] = {bq.x, bq.y, bq.z, bq.w};
#pragma unroll
      for (int i = 0; i < 4; i++)
#pragma unroll
        for (int j = 0; j < 4; j++)
          acc[i][j] = fmaf(aa[i], bb[j], acc[i][j]);
    }
    __syncthreads();
  }
#pragma unroll
  for (int i = 0; i < 4; i++)
#pragma unroll
    for (int j = 0; j < 4; j++)
      if (n0 + tx*4 + j < N)
        C[(size_t)(m0 + ty*4 + i)*N + n0 + tx*4 + j] = acc[i][j];
}

// ---------------- depthwise causal conv(4) + silu + transpose -> g_ut[b,d,t] ----------------
__global__ void conv_kernel(const float* __restrict__ conv_w, const float* __restrict__ conv_b) {
  __shared__ float sx[67][33];
  int b = blockIdx.z, t0 = blockIdx.x * 64, d0 = blockIdx.y * 32;
  int tid = threadIdx.y * 64 + threadIdx.x;
  for (int i = tid; i < 67*32; i += 256) {
    int r = i >> 5, c = i & 31;
    int t = t0 - 3 + r;
    sx[r][c] = (t >= 0) ? g_xz[(size_t)(b*SEQ + t)*2*DINNER + d0 + c] : 0.f;
  }
  __syncthreads();
  int tx = threadIdx.x;
#pragma unroll
  for (int i = 0; i < 8; i++) {
    int dl = threadIdx.y * 8 + i;
    int d = d0 + dl;
    float w0 = conv_w[d*4+0], w1 = conv_w[d*4+1], w2 = conv_w[d*4+2], w3 = conv_w[d*4+3];
    float acc = conv_b[d];
    acc += sx[tx+0][dl]*w0 + sx[tx+1][dl]*w1 + sx[tx+2][dl]*w2 + sx[tx+3][dl]*w3;
    g_ut[(size_t)(b*DINNER + d)*SEQ + t0 + tx] = siluf(acc);
  }
}

// ---------------- silu(z) transpose -> g_zt[b,d,t] ----------------
__global__ void ztrans_kernel() {
  __shared__ float s[32][33];
  int b = blockIdx.z, t0 = blockIdx.x * 32, d0 = blockIdx.y * 32;
  int tx = threadIdx.x, ty = threadIdx.y;
#pragma unroll
  for (int i = 0; i < 4; i++) {
    int r = ty * 4 + i;
    s[r][tx] = g_xz[(size_t)(b*SEQ + t0 + r)*2*DINNER + DINNER + d0 + tx];
  }
  __syncthreads();
#pragma unroll
  for (int i = 0; i < 4; i++) {
    int dl = ty * 4 + i;
    g_zt[(size_t)(b*DINNER + d0 + dl)*SEQ + t0 + tx] = siluf(s[tx][dl]);
  }
}

// ---------------- delta = softplus(dt @ dt_proj_w^T + b), transposed write ----------------
__global__ void delta_kernel(const float* __restrict__ dtw, const float* __restrict__ dtb) {
  __shared__ float sdt[32][33];
  __shared__ float sw[32][33];
  int b = blockIdx.z, t0 = blockIdx.x * 32, d0 = blockIdx.y * 32;
  int tx = threadIdx.x, ty = threadIdx.y;
  int tid = ty * 32 + tx;
  for (int i = tid; i < 32*32; i += 256) {
    int q = i >> 5, r = i & 31;
    sdt[q][r] = g_dbc[(size_t)(b*SEQ + t0 + q)*DBC_W + r];
    sw[q][r]  = dtw[(d0 + q)*DTRANK + r];
  }
  __syncthreads();
#pragma unroll
  for (int i = 0; i < 4; i++) {
    int dl = ty * 4 + i;
    float acc = dtb[d0 + dl];
#pragma unroll
    for (int r = 0; r < 32; r++)
      acc = fmaf(sdt[tx][r], sw[dl][r], acc);
    g_deltat[(size_t)(b*DINNER + d0 + dl)*SEQ + t0 + tx] = softplusf(acc);
  }
}

// ---------------- selective scan: one warp per (b,d) ----------------
__global__ void scan_kernel(const float* __restrict__ Dw, const float* __restrict__ A_log) {
  int warp = threadIdx.x >> 5, lane = threadIdx.x & 31;
  int g = blockIdx.x * 8 + warp;
  int b = g >> 10, d = g & 1023;
  __shared__ float sBC[32][64];
  float An = -__expf(A_log[d*DSTATE + lane]);
  float Dd = Dw[d];
  float h = 0.f;
  const float* ut  = g_ut     + (size_t)(b*DINNER + d)*SEQ;
  const float* dtp = g_deltat + (size_t)(b*DINNER + d)*SEQ;
  const float* ztp = g_zt     + (size_t)(b*DINNER + d)*SEQ;
  float*       ytp = g_yt     + (size_t)(b*DINNER + d)*SEQ;

  for (int t0 = 0; t0 < SEQ; t0 += 32) {
    __syncthreads();
    for (int i = threadIdx.x; i < 32*64; i += 256) {
      int s = i >> 6, c = i & 63;
      sBC[s][c] = g_dbc[(size_t)(b*SEQ + t0 + s)*DBC_W + DSTATE + c];
    }
    __syncthreads();
    float du = ut[t0 + lane];
    float dd = dtp[t0 + lane];
    float sz = ztp[t0 + lane];   // already silu'd
    float yreg = 0.f;
#pragma unroll 8
    for (int s = 0; s < 32; s++) {
      float delta_t = __shfl_sync(0xffffffffu, dd, s);
      float u_t     = __shfl_sync(0xffffffffu, du, s);
      float Bv = sBC[s][lane];
      float Cv = sBC[s][32 + lane];
      float dA = __expf(delta_t * An);
      h = fmaf(dA, h, delta_t * u_t * Bv);
      float p = h * Cv;
      p += __shfl_xor_sync(0xffffffffu, p, 16);
      p += __shfl_xor_sync(0xffffffffu, p, 8);
      p += __shfl_xor_sync(0xffffffffu, p, 4);
      p += __shfl_xor_sync(0xffffffffu, p, 2);
      p += __shfl_xor_sync(0xffffffffu, p, 1);
      if (lane == s) yreg = (p + du * Dd) * sz;   // lane s owns t0+s: du/sz are its own
    }
    ytp[t0 + lane] = yreg;
  }
}

// ---------------- layernorm over 512 ----------------
__global__ void ln_kernel(const float* __restrict__ lnw, const float* __restrict__ lnb) {
  int row = blockIdx.x;
  const float* y = g_y2 + (size_t)row * DMODEL;
  float*       o = g_yn + (size_t)row * DMODEL;
  int tid = threadIdx.x;           // 128 threads
  int lane = tid & 31, wid = tid >> 5;
  float v[4], s = 0.f, s2 = 0.f;
#pragma unroll
  for (int i = 0; i < 4; i++) {
    float x = y[tid + i*128];
    v[i] = x; s += x; s2 += x*x;
  }
#pragma unroll
  for (int off = 16; off >= 1; off >>= 1) {
    s  += __shfl_xor_sync(0xffffffffu, s, off);
    s2 += __shfl_xor_sync(0xffffffffu, s2, off);
  }
  __shared__ float sh[10];
  if (lane == 0) { sh[wid] = s; sh[4 + wid] = s2; }
  __syncthreads();
  if (tid == 0) {
    float ts = sh[0] + sh[1] + sh[2] + sh[3];
    float ts2 = sh[4] + sh[5] + sh[6] + sh[7];
    float mu = ts * (1.f/DMODEL);
    float var = ts2 * (1.f/DMODEL) - mu*mu;
    sh[8] = mu;
    sh[9] = rsqrtf(var + 1e-5f);
  }
  __syncthreads();
  float mu = sh[8], inv = sh[9];
#pragma unroll
  for (int i = 0; i < 4; i++) {
    int c = tid + i*128;
    o[c] = (v[i] - mu) * inv * lnw[c] + lnb[c];
  }
}

// ---------------- gelu + bias + residual + inverse-perm scatter ----------------
__global__ void final_kernel(const float* __restrict__ lin_b, float* __restrict__ out) {
  int e = blockIdx.x * 256 + threadIdx.x;
  int c  = e & (DMODEL - 1);
  int bp = e >> 9;
  int b  = bp >> 10, p = bp & (SEQ - 1);
  int src = perm_src(p);                 // perm[p]
  float x = g_lin[e] + lin_b[c];
  float gl = 0.5f * x * (1.f + erff(x * 0.70710678118654752f));
  out[(size_t)(b*SEQ + src)*DMODEL + c] = gl + g_xperm[e];
}

// ---------------- launch ----------------
extern "C" void kernel_launch(void* const* d_in, const int* in_sizes, int n_in,
                              void* d_out, int out_size) {
  const float* tokens     = (const float*)d_in[0];
  const float* in_proj_w  = (const float*)d_in[1];
  const float* conv_w     = (const float*)d_in[2];
  const float* conv_b     = (const float*)d_in[3];
  const float* x_proj_w   = (const float*)d_in[4];
  const float* dt_proj_w  = (const float*)d_in[5];
  const float* dt_proj_b  = (const float*)d_in[6];
  const float* A_log      = (const float*)d_in[7];
  const float* Dw         = (const float*)d_in[8];
  const float* out_proj_w = (const float*)d_in[9];
  const float* ln_w       = (const float*)d_in[10];
  const float* ln_b       = (const float*)d_in[11];
  const float* lin_w      = (const float*)d_in[12];
  const float* lin_b      = (const float*)d_in[13];
  float* out = (float*)d_out;

  float *p_xperm, *p_xz, *p_ut, *p_dbc, *p_yt, *p_y2, *p_yn, *p_lin;
  cudaGetSymbolAddress((void**)&p_xperm, g_xperm);
  cudaGetSymbolAddress((void**)&p_xz,    g_xz);
  cudaGetSymbolAddress((void**)&p_ut,    g_ut);
  cudaGetSymbolAddress((void**)&p_dbc,   g_dbc);
  cudaGetSymbolAddress((void**)&p_yt,    g_yt);
  cudaGetSymbolAddress((void**)&p_y2,    g_y2);
  cudaGetSymbolAddress((void**)&p_yn,    g_yn);
  cudaGetSymbolAddress((void**)&p_lin,   g_lin);

  // 1. permute
  permute_kernel<<<NROWS*DMODEL/256, 256>>>(tokens);
  // 2. xz = xperm @ in_proj_w^T   [4096 x 2048 x 512]
  sgemm_nt<<<dim3(2*DINNER/64, NROWS/64), 256>>>(p_xperm, in_proj_w, p_xz, NROWS, 2*DINNER, DMODEL);
  // 3. conv + silu -> ut[b,d,t]
  conv_kernel<<<dim3(SEQ/64, DINNER/32, BATCH), dim3(64,4)>>>(conv_w, conv_b);
  // 3b. silu(z) -> zt[b,d,t]
  ztrans_kernel<<<dim3(SEQ/32, DINNER/32, BATCH), dim3(32,8)>>>();
  // 4. dbc = u @ x_proj_w^T   [per-b: 1024 x 96 x 1024], A transposed layout
  sgemm_tn<<<dim3(2, SEQ/64, BATCH), 256>>>(p_ut, x_proj_w, p_dbc, SEQ, DBC_W, DINNER,
                                            DINNER*SEQ, SEQ*DBC_W);
  // 5. delta (softplus) -> deltat[b,d,t]
  delta_kernel<<<dim3(SEQ/32, DINNER/32, BATCH), dim3(32,8)>>>(dt_proj_w, dt_proj_b);
  // 6. selective scan -> yt[b,d,t]  (includes +u*D and *silu(z))
  scan_kernel<<<NROWS/8, 256>>>(Dw, A_log);
  // 7. y2 = y @ out_proj_w^T  [per-b: 1024 x 512 x 1024]
  sgemm_tn<<<dim3(DMODEL/64, SEQ/64, BATCH), 256>>>(p_yt, out_proj_w, p_y2, SEQ, DMODEL, DINNER,
                                                    DINNER*SEQ, SEQ*DMODEL);
  // 8. layernorm
  ln_kernel<<<NROWS, 128>>>(ln_w, ln_b);
  // 9. lin = yn @ lin_w^T  [4096 x 512 x 512]
  sgemm_nt<<<dim3(DMODEL/64, NROWS/64), 256>>>(p_yn, lin_w, p_lin, NROWS, DMODEL, DMODEL);
  // 10. gelu + bias + residual + inverse-permute scatter
  final_kernel<<<NROWS*DMODEL/256, 256>>>(lin_b, out);
}

// round 3
// speedup vs baseline: 1.8024x; 1.8024x over previous
#include <cuda_runtime.h>
#include <cstdint>
#include <math.h>

#define BATCH  4
#define SEQ    1024
#define DMODEL 512
#define DINNER 1024
#define DSTATE 32
#define DTRANK 32
#define DBC_W  96
#define NROWS  (BATCH*SEQ)   // 4096

// ================= scratch =================
__device__ float g_xperm [BATCH*SEQ*DMODEL];
__device__ float g_xz    [BATCH*SEQ*2*DINNER];
__device__ float g_ut    [BATCH*DINNER*SEQ];
__device__ float g_zt    [BATCH*DINNER*SEQ];
__device__ float g_dbc   [BATCH*SEQ*DBC_W];
__device__ float g_deltat[BATCH*DINNER*SEQ];
__device__ float g_yt    [BATCH*DINNER*SEQ];
__device__ float g_y2    [BATCH*SEQ*DMODEL];
__device__ float g_yn    [BATCH*SEQ*DMODEL];
__device__ float g_lin   [BATCH*SEQ*DMODEL];

__device__ __forceinline__ int perm_src(int p) {
  int r = p >> 5, c = p & 31;
  if (r & 1) c = 31 - c;
  return (r << 5) | c;
}
__device__ __forceinline__ float softplusf(float x) {
  return fmaxf(x, 0.f) + log1pf(expf(-fabsf(x)));
}
__device__ __forceinline__ float siluf(float x) {
  return x / (1.f + expf(-x));
}
__device__ __forceinline__ float to_tf32(float x) {
  uint32_t u;
  asm("cvt.rna.tf32.f32 %0, %1;" : "=r"(u) : "f"(x));
  return __uint_as_float(u);
}
__device__ __forceinline__ void mma_tf32(float* c, const uint32_t* a, const uint32_t* b) {
  asm volatile(
    "mma.sync.aligned.m16n8k8.row.col.f32.tf32.tf32.f32 "
    "{%0,%1,%2,%3}, {%4,%5,%6,%7}, {%8,%9}, {%0,%1,%2,%3};"
    : "+f"(c[0]), "+f"(c[1]), "+f"(c[2]), "+f"(c[3])
    : "r"(a[0]), "r"(a[1]), "r"(a[2]), "r"(a[3]), "r"(b[0]), "r"(b[1]));
}

// ================= tf32 mma.sync GEMM =================
// Block tile 128x128, k-chunk 32. 8 warps (4 M x 2 N), warp tile 32x64.
// Smem stride 36 floats -> fragment LDS bank = 4*group+tg (conflict-free).
#define KCH 32

// C[M,N] = A[M,K] * B[N,K]^T ; all row-major. M%128==0, N%128==0, K%32==0.
__global__ __launch_bounds__(256) void gemm_mma_nt(const float* __restrict__ A,
    const float* __restrict__ B, float* __restrict__ C, int M, int N, int K) {
  __shared__ float As[128][36];
  __shared__ float Bs[128][36];
  const int tid = threadIdx.x;
  const int wid = tid >> 5, lane = tid & 31;
  const int wm = wid & 3, wn = wid >> 2;
  const int group = lane >> 2, tg = lane & 3;
  const int m0 = blockIdx.y * 128, n0 = blockIdx.x * 128;
  const int lr = tid >> 3, lk = tid & 7;

  float acc[2][8][4];
#pragma unroll
  for (int i = 0; i < 2; i++)
#pragma unroll
    for (int j = 0; j < 8; j++)
#pragma unroll
      for (int q = 0; q < 4; q++) acc[i][j][q] = 0.f;

  for (int k0 = 0; k0 < K; k0 += KCH) {
    __syncthreads();
#pragma unroll
    for (int pass = 0; pass < 4; ++pass) {
      int r = lr + pass * 32;
      float4 v = *(const float4*)&A[(size_t)(m0 + r) * K + k0 + lk * 4];
      v.x = to_tf32(v.x); v.y = to_tf32(v.y); v.z = to_tf32(v.z); v.w = to_tf32(v.w);
      *(float4*)&As[r][lk * 4] = v;
      float4 w = *(const float4*)&B[(size_t)(n0 + r) * K + k0 + lk * 4];
      w.x = to_tf32(w.x); w.y = to_tf32(w.y); w.z = to_tf32(w.z); w.w = to_tf32(w.w);
      *(float4*)&Bs[r][lk * 4] = w;
    }
    __syncthreads();
#pragma unroll
    for (int ks = 0; ks < 4; ++ks) {
      int kk = ks * 8;
      uint32_t af[2][4], bf[8][2];
#pragma unroll
      for (int i = 0; i < 2; i++) {
        int mr = wm * 32 + i * 16;
        af[i][0] = __float_as_uint(As[mr + group    ][kk + tg    ]);
        af[i][1] = __float_as_uint(As[mr + group + 8][kk + tg    ]);
        af[i][2] = __float_as_uint(As[mr + group    ][kk + tg + 4]);
        af[i][3] = __float_as_uint(As[mr + group + 8][kk + tg + 4]);
      }
#pragma unroll
      for (int j = 0; j < 8; j++) {
        int nr = wn * 64 + j * 8;
        bf[j][0] = __float_as_uint(Bs[nr + group][kk + tg    ]);
        bf[j][1] = __float_as_uint(Bs[nr + group][kk + tg + 4]);
      }
#pragma unroll
      for (int i = 0; i < 2; i++)
#pragma unroll
        for (int j = 0; j < 8; j++)
          mma_tf32(acc[i][j], af[i], bf[j]);
    }
  }
#pragma unroll
  for (int i = 0; i < 2; i++) {
    int row0 = m0 + wm * 32 + i * 16 + group;
#pragma unroll
    for (int j = 0; j < 8; j++) {
      int col = n0 + wn * 64 + j * 8 + tg * 2;
      *(float2*)&C[(size_t)row0 * N + col]       = make_float2(acc[i][j][0], acc[i][j][1]);
      *(float2*)&C[(size_t)(row0 + 8) * N + col] = make_float2(acc[i][j][2], acc[i][j][3]);
    }
  }
}

// C[M,N] = At^T * B^T ; At is [K, lda] (m contiguous), B is [N,K]; batched via z.
// N may be < 128 (guarded). M%128==0, K%32==0.
__global__ __launch_bounds__(256) void gemm_mma_tn(const float* __restrict__ At,
    const float* __restrict__ B, float* __restrict__ C, int M, int N, int K,
    int lda, int sA, int sC) {
  At += (size_t)blockIdx.z * sA;
  C  += (size_t)blockIdx.z * sC;
  __shared__ float As[128][36];
  __shared__ float Bs[128][36];
  const int tid = threadIdx.x;
  const int wid = tid >> 5, lane = tid & 31;
  const int wm = wid & 3, wn = wid >> 2;
  const int group = lane >> 2, tg = lane & 3;
  const int m0 = blockIdx.y * 128, n0 = blockIdx.x * 128;
  const int lr = tid >> 3, lk = tid & 7;
  const int kkl = lane >> 3, mcl = lane & 7;

  float acc[2][8][4];
#pragma unroll
  for (int i = 0; i < 2; i++)
#pragma unroll
    for (int j = 0; j < 8; j++)
#pragma unroll
      for (int q = 0; q < 4; q++) acc[i][j][q] = 0.f;

  for (int k0 = 0; k0 < K; k0 += KCH) {
    __syncthreads();
    // A: transpose [k][m] -> As[m][k]
    {
      int kk = wid * 4 + kkl;                  // 0..31
#pragma unroll
      for (int pass = 0; pass < 4; ++pass) {
        int mc = pass * 8 + mcl;               // float4 chunk of m, 0..31
        float4 v = *(const float4*)&At[(size_t)(k0 + kk) * lda + m0 + mc * 4];
        As[mc * 4 + 0][kk] = to_tf32(v.x);
        As[mc * 4 + 1][kk] = to_tf32(v.y);
        As[mc * 4 + 2][kk] = to_tf32(v.z);
        As[mc * 4 + 3][kk] = to_tf32(v.w);
      }
    }
#pragma unroll
    for (int pass = 0; pass < 4; ++pass) {
      int r = lr + pass * 32;
      float4 w = make_float4(0.f, 0.f, 0.f, 0.f);
      if (n0 + r < N) w = *(const float4*)&B[(size_t)(n0 + r) * K + k0 + lk * 4];
      w.x = to_tf32(w.x); w.y = to_tf32(w.y); w.z = to_tf32(w.z); w.w = to_tf32(w.w);
      *(float4*)&Bs[r][lk * 4] = w;
    }
    __syncthreads();
#pragma unroll
    for (int ks = 0; ks < 4; ++ks) {
      int kk = ks * 8;
      uint32_t af[2][4], bf[8][2];
#pragma unroll
      for (int i = 0; i < 2; i++) {
        int mr = wm * 32 + i * 16;
        af[i][0] = __float_as_uint(As[mr + group    ][kk + tg    ]);
        af[i][1] = __float_as_uint(As[mr + group + 8][kk + tg    ]);
        af[i][2] = __float_as_uint(As[mr + group    ][kk + tg + 4]);
        af[i][3] = __float_as_uint(As[mr + group + 8][kk + tg + 4]);
      }
#pragma unroll
      for (int j = 0; j < 8; j++) {
        int nr = wn * 64 + j * 8;
        bf[j][0] = __float_as_uint(Bs[nr + group][kk + tg    ]);
        bf[j][1] = __float_as_uint(Bs[nr + group][kk + tg + 4]);
      }
#pragma unroll
      for (int i = 0; i < 2; i++)
#pragma unroll
        for (int j = 0; j < 8; j++)
          mma_tf32(acc[i][j], af[i], bf[j]);
    }
  }
#pragma unroll
  for (int i = 0; i < 2; i++) {
    int row0 = m0 + wm * 32 + i * 16 + group;
#pragma unroll
    for (int j = 0; j < 8; j++) {
      int col = n0 + wn * 64 + j * 8 + tg * 2;
      if (col < N) {
        *(float2*)&C[(size_t)row0 * N + col]       = make_float2(acc[i][j][0], acc[i][j][1]);
        *(float2*)&C[(size_t)(row0 + 8) * N + col] = make_float2(acc[i][j][2], acc[i][j][3]);
      }
    }
  }
}

// ================= elementwise / small kernels =================
__global__ void permute_kernel(const float* __restrict__ tokens) {
  int e = blockIdx.x * 256 + threadIdx.x;
  int c  = e & (DMODEL - 1);
  int bp = e >> 9;
  int b  = bp >> 10, p = bp & (SEQ - 1);
  int src = perm_src(p);
  g_xperm[e] = tokens[(b*SEQ + src)*DMODEL + c];
}

__global__ void conv_kernel(const float* __restrict__ conv_w, const float* __restrict__ conv_b) {
  __shared__ float sx[67][33];
  int b = blockIdx.z, t0 = blockIdx.x * 64, d0 = blockIdx.y * 32;
  int tid = threadIdx.y * 64 + threadIdx.x;
  for (int i = tid; i < 67*32; i += 256) {
    int r = i >> 5, c = i & 31;
    int t = t0 - 3 + r;
    sx[r][c] = (t >= 0) ? g_xz[(size_t)(b*SEQ + t)*2*DINNER + d0 + c] : 0.f;
  }
  __syncthreads();
  int tx = threadIdx.x;
#pragma unroll
  for (int i = 0; i < 8; i++) {
    int dl = threadIdx.y * 8 + i;
    int d = d0 + dl;
    float w0 = conv_w[d*4+0], w1 = conv_w[d*4+1], w2 = conv_w[d*4+2], w3 = conv_w[d*4+3];
    float acc = conv_b[d];
    acc += sx[tx+0][dl]*w0 + sx[tx+1][dl]*w1 + sx[tx+2][dl]*w2 + sx[tx+3][dl]*w3;
    g_ut[(size_t)(b*DINNER + d)*SEQ + t0 + tx] = siluf(acc);
  }
}

__global__ void ztrans_kernel() {
  __shared__ float s[32][33];
  int b = blockIdx.z, t0 = blockIdx.x * 32, d0 = blockIdx.y * 32;
  int tx = threadIdx.x, ty = threadIdx.y;
#pragma unroll
  for (int i = 0; i < 4; i++) {
    int r = ty * 4 + i;
    s[r][tx] = g_xz[(size_t)(b*SEQ + t0 + r)*2*DINNER + DINNER + d0 + tx];
  }
  __syncthreads();
#pragma unroll
  for (int i = 0; i < 4; i++) {
    int dl = ty * 4 + i;
    g_zt[(size_t)(b*DINNER + d0 + dl)*SEQ + t0 + tx] = siluf(s[tx][dl]);
  }
}

__global__ void delta_kernel(const float* __restrict__ dtw, const float* __restrict__ dtb) {
  __shared__ float sdt[32][33];
  __shared__ float sw[32][33];
  int b = blockIdx.z, t0 = blockIdx.x * 32, d0 = blockIdx.y * 32;
  int tx = threadIdx.x, ty = threadIdx.y;
  int tid = ty * 32 + tx;
  for (int i = tid; i < 32*32; i += 256) {
    int q = i >> 5, r = i & 31;
    sdt[q][r] = g_dbc[(size_t)(b*SEQ + t0 + q)*DBC_W + r];
    sw[q][r]  = dtw[(d0 + q)*DTRANK + r];
  }
  __syncthreads();
#pragma unroll
  for (int i = 0; i < 4; i++) {
    int dl = ty * 4 + i;
    float acc = dtb[d0 + dl];
#pragma unroll
    for (int r = 0; r < 32; r++)
      acc = fmaf(sdt[tx][r], sw[dl][r], acc);
    g_deltat[(size_t)(b*DINNER + d0 + dl)*SEQ + t0 + tx] = softplusf(acc);
  }
}

__global__ void scan_kernel(const float* __restrict__ Dw, const float* __restrict__ A_log) {
  int warp = threadIdx.x >> 5, lane = threadIdx.x & 31;
  int g = blockIdx.x * 8 + warp;
  int b = g >> 10, d = g & 1023;
  __shared__ float sBC[32][64];
  float An = -__expf(A_log[d*DSTATE + lane]);
  float Dd = Dw[d];
  float h = 0.f;
  const float* ut  = g_ut     + (size_t)(b*DINNER + d)*SEQ;
  const float* dtp = g_deltat + (size_t)(b*DINNER + d)*SEQ;
  const float* ztp = g_zt     + (size_t)(b*DINNER + d)*SEQ;
  float*       ytp = g_yt     + (size_t)(b*DINNER + d)*SEQ;

  for (int t0 = 0; t0 < SEQ; t0 += 32) {
    __syncthreads();
    for (int i = threadIdx.x; i < 32*64; i += 256) {
      int s = i >> 6, c = i & 63;
      sBC[s][c] = g_dbc[(size_t)(b*SEQ + t0 + s)*DBC_W + DSTATE + c];
    }
    __syncthreads();
    float du = ut[t0 + lane];
    float dd = dtp[t0 + lane];
    float sz = ztp[t0 + lane];
    float yreg = 0.f;
#pragma unroll 8
    for (int s = 0; s < 32; s++) {
      float delta_t = __shfl_sync(0xffffffffu, dd, s);
      float u_t     = __shfl_sync(0xffffffffu, du, s);
      float Bv = sBC[s][lane];
      float Cv = sBC[s][32 + lane];
      float dA = __expf(delta_t * An);
      h = fmaf(dA, h, delta_t * u_t * Bv);
      float pp = h * Cv;
      pp += __shfl_xor_sync(0xffffffffu, pp, 16);
      pp += __shfl_xor_sync(0xffffffffu, pp, 8);
      pp += __shfl_xor_sync(0xffffffffu, pp, 4);
      pp += __shfl_xor_sync(0xffffffffu, pp, 2);
      pp += __shfl_xor_sync(0xffffffffu, pp, 1);
      if (lane == s) yreg = (pp + du * Dd) * sz;
    }
    ytp[t0 + lane] = yreg;
  }
}

__global__ void ln_kernel(const float* __restrict__ lnw, const float* __restrict__ lnb) {
  int row = blockIdx.x;
  const float* y = g_y2 + (size_t)row * DMODEL;
  float*       o = g_yn + (size_t)row * DMODEL;
  int tid = threadIdx.x;
  int lane = tid & 31, wid = tid >> 5;
  float v[4], s = 0.f, s2 = 0.f;
#pragma unroll
  for (int i = 0; i < 4; i++) {
    float x = y[tid + i*128];
    v[i] = x; s += x; s2 += x*x;
  }
#pragma unroll
  for (int off = 16; off >= 1; off >>= 1) {
    s  += __shfl_xor_sync(0xffffffffu, s, off);
    s2 += __shfl_xor_sync(0xffffffffu, s2, off);
  }
  __shared__ float sh[10];
  if (lane == 0) { sh[wid] = s; sh[4 + wid] = s2; }
  __syncthreads();
  if (tid == 0) {
    float ts = sh[0] + sh[1] + sh[2] + sh[3];
    float ts2 = sh[4] + sh[5] + sh[6] + sh[7];
    float mu = ts * (1.f/DMODEL);
    float var = ts2 * (1.f/DMODEL) - mu*mu;
    sh[8] = mu;
    sh[9] = rsqrtf(var + 1e-5f);
  }
  __syncthreads();
  float mu = sh[8], inv = sh[9];
#pragma unroll
  for (int i = 0; i < 4; i++) {
    int c = tid + i*128;
    o[c] = (v[i] - mu) * inv * lnw[c] + lnb[c];
  }
}

__global__ void final_kernel(const float* __restrict__ lin_b, float* __restrict__ out) {
  int e = blockIdx.x * 256 + threadIdx.x;
  int c  = e & (DMODEL - 1);
  int bp = e >> 9;
  int b  = bp >> 10, p = bp & (SEQ - 1);
  int src = perm_src(p);
  float x = g_lin[e] + lin_b[c];
  float gl = 0.5f * x * (1.f + erff(x * 0.70710678118654752f));
  out[(size_t)(b*SEQ + src)*DMODEL + c] = gl + g_xperm[e];
}

// ================= launch =================
extern "C" void kernel_launch(void* const* d_in, const int* in_sizes, int n_in,
                              void* d_out, int out_size) {
  const float* tokens     = (const float*)d_in[0];
  const float* in_proj_w  = (const float*)d_in[1];
  const float* conv_w     = (const float*)d_in[2];
  const float* conv_b     = (const float*)d_in[3];
  const float* x_proj_w   = (const float*)d_in[4];
  const float* dt_proj_w  = (const float*)d_in[5];
  const float* dt_proj_b  = (const float*)d_in[6];
  const float* A_log      = (const float*)d_in[7];
  const float* Dw         = (const float*)d_in[8];
  const float* out_proj_w = (const float*)d_in[9];
  const float* ln_w       = (const float*)d_in[10];
  const float* ln_b       = (const float*)d_in[11];
  const float* lin_w      = (const float*)d_in[12];
  const float* lin_b      = (const float*)d_in[13];
  float* out = (float*)d_out;

  float *p_xperm, *p_xz, *p_ut, *p_dbc, *p_yt, *p_y2, *p_yn, *p_lin;
  cudaGetSymbolAddress((void**)&p_xperm, g_xperm);
  cudaGetSymbolAddress((void**)&p_xz,    g_xz);
  cudaGetSymbolAddress((void**)&p_ut,    g_ut);
  cudaGetSymbolAddress((void**)&p_dbc,   g_dbc);
  cudaGetSymbolAddress((void**)&p_yt,    g_yt);
  cudaGetSymbolAddress((void**)&p_y2,    g_y2);
  cudaGetSymbolAddress((void**)&p_yn,    g_yn);
  cudaGetSymbolAddress((void**)&p_lin,   g_lin);

  // 1. permute
  permute_kernel<<<NROWS*DMODEL/256, 256>>>(tokens);
  // 2. xz = xperm @ in_proj_w^T   [4096 x 2048 x 512]
  gemm_mma_nt<<<dim3(2*DINNER/128, NROWS/128), 256>>>(p_xperm, in_proj_w, p_xz,
                                                      NROWS, 2*DINNER, DMODEL);
  // 3. conv + silu -> ut[b,d,t]
  conv_kernel<<<dim3(SEQ/64, DINNER/32, BATCH), dim3(64,4)>>>(conv_w, conv_b);
  // 3b. silu(z) -> zt[b,d,t]
  ztrans_kernel<<<dim3(SEQ/32, DINNER/32, BATCH), dim3(32,8)>>>();
  // 4. dbc = u @ x_proj_w^T   [per-b: 1024 x 96 x 1024], A is [K,M] (ut)
  gemm_mma_tn<<<dim3(1, SEQ/128, BATCH), 256>>>(p_ut, x_proj_w, p_dbc,
                                                SEQ, DBC_W, DINNER,
                                                SEQ, DINNER*SEQ, SEQ*DBC_W);
  // 5. delta
  delta_kernel<<<dim3(SEQ/32, DINNER/32, BATCH), dim3(32,8)>>>(dt_proj_w, dt_proj_b);
  // 6. scan -> yt[b,d,t]
  scan_kernel<<<NROWS/8, 256>>>(Dw, A_log);
  // 7. y2 = y @ out_proj_w^T  [per-b: 1024 x 512 x 1024], A is [K,M] (yt)
  gemm_mma_tn<<<dim3(DMODEL/128, SEQ/128, BATCH), 256>>>(p_yt, out_proj_w, p_y2,
                                                         SEQ, DMODEL, DINNER,
                                                         SEQ, DINNER*SEQ, SEQ*DMODEL);
  // 8. layernorm
  ln_kernel<<<NROWS, 128>>>(ln_w, ln_b);
  // 9. lin = yn @ lin_w^T  [4096 x 512 x 512]
  gemm_mma_nt<<<dim3(DMODEL/128, NROWS/128), 256>>>(p_yn, lin_w, p_lin,
                                                    NROWS, DMODEL, DMODEL);
  // 10. gelu + bias + residual + inverse-permute scatter
  final_kernel<<<NROWS*DMODEL/256, 256>>>(lin_b, out);
}

// round 4
// speedup vs baseline: 1.9998x; 1.1095x over previous
#include <cuda_runtime.h>
#include <cstdint>
#include <math.h>

#define BATCH  4
#define SEQ    1024
#define DMODEL 512
#define DINNER 1024
#define DSTATE 32
#define DTRANK 32
#define DBC_W  96
#define NROWS  (BATCH*SEQ)   // 4096

// ================= scratch =================
__device__ float g_xz    [BATCH*SEQ*2*DINNER];
__device__ float g_ut    [BATCH*DINNER*SEQ];
__device__ float g_zt    [BATCH*DINNER*SEQ];
__device__ float g_dbc   [BATCH*SEQ*DBC_W];
__device__ float g_deltat[BATCH*DINNER*SEQ];
__device__ float g_yt    [BATCH*DINNER*SEQ];
__device__ float g_y2    [BATCH*SEQ*DMODEL];
__device__ float g_yn    [BATCH*SEQ*DMODEL];
__device__ float g_lin   [BATCH*SEQ*DMODEL];

__device__ __forceinline__ int perm_src(int p) {
  int r = p >> 5, c = p & 31;
  if (r & 1) c = 31 - c;
  return (r << 5) | c;
}
__device__ __forceinline__ int remap_row(int m) {   // (b,p) -> b*SEQ + perm[p]
  return (m & ~(SEQ - 1)) + perm_src(m & (SEQ - 1));
}
__device__ __forceinline__ float softplusf(float x) {
  return fmaxf(x, 0.f) + log1pf(expf(-fabsf(x)));
}
__device__ __forceinline__ float siluf(float x) {
  return x / (1.f + expf(-x));
}
__device__ __forceinline__ uint32_t smem_u32(const void* p) {
  uint32_t a;
  asm("{ .reg .u64 t; cvta.to.shared.u64 t, %1; cvt.u32.u64 %0, t; }" : "=r"(a) : "l"(p));
  return a;
}
__device__ __forceinline__ void cp16(void* dst, const void* src) {
  asm volatile("cp.async.cg.shared.global [%0], [%1], 16;"
               :: "r"(smem_u32(dst)), "l"(src));
}
__device__ __forceinline__ void cp16z(void* dst, const void* src, bool valid) {
  int sz = valid ? 16 : 0;
  asm volatile("cp.async.cg.shared.global [%0], [%1], 16, %2;"
               :: "r"(smem_u32(dst)), "l"(src), "r"(sz));
}
#define CP_COMMIT() asm volatile("cp.async.commit_group;" ::: "memory")
#define CP_WAIT1()  asm volatile("cp.async.wait_group 1;" ::: "memory")
#define CP_WAIT0()  asm volatile("cp.async.wait_group 0;" ::: "memory")

__device__ __forceinline__ void mma_tf32(float* c, const uint32_t* a, const uint32_t* b) {
  asm volatile(
    "mma.sync.aligned.m16n8k8.row.col.f32.tf32.tf32.f32 "
    "{%0,%1,%2,%3}, {%4,%5,%6,%7}, {%8,%9}, {%0,%1,%2,%3};"
    : "+f"(c[0]), "+f"(c[1]), "+f"(c[2]), "+f"(c[3])
    : "r"(a[0]), "r"(a[1]), "r"(a[2]), "r"(a[3]), "r"(b[0]), "r"(b[1]));
}

// ================= GEMM NT: C[M,N] = A[M,K] @ B[N,K]^T =================
// 128x128x32 tiles, 8 warps (4M x 2N), warp tile 32x64, cp.async 2-stage.
// gatherA != 0 -> A row index passed through remap_row (fused permutation).
#define NT_SMEM (2*128*36*2*4)
__global__ __launch_bounds__(256) void gemm_nt(const float* __restrict__ A,
    const float* __restrict__ B, float* __restrict__ C, int M, int N, int K,
    int gatherA) {
  extern __shared__ float sm[];
  float (*As)[128][36] = (float(*)[128][36])sm;
  float (*Bs)[128][36] = (float(*)[128][36])(sm + 2*128*36);
  const int tid = threadIdx.x;
  const int wid = tid >> 5, lane = tid & 31;
  const int wm = wid & 3, wn = wid >> 2;
  const int group = lane >> 2, tg = lane & 3;
  const int m0 = blockIdx.y * 128, n0 = blockIdx.x * 128;
  const int lr = tid >> 3, lk = tid & 7;
  const int KC = K / 32;

  float acc[2][8][4] = {};

  // row sources for this thread's 4 A-load rows (gather applied once)
  int arow[4];
#pragma unroll
  for (int pass = 0; pass < 4; ++pass) {
    int m = m0 + lr + pass * 32;
    arow[pass] = gatherA ? remap_row(m) : m;
  }

#define NT_LOAD(c) do { \
    int k0 = (c) * 32; int bf_ = (c) & 1; \
    _Pragma("unroll") \
    for (int pass = 0; pass < 4; ++pass) { \
      int r = lr + pass * 32; \
      cp16(&As[bf_][r][lk*4], &A[(size_t)arow[pass]*K + k0 + lk*4]); \
      cp16z(&Bs[bf_][r][lk*4], &B[(size_t)(n0 + r)*K + k0 + lk*4], n0 + r < N); \
    } \
    CP_COMMIT(); \
  } while (0)

  NT_LOAD(0);
  for (int c = 0; c < KC; ++c) {
    if (c + 1 < KC) { NT_LOAD(c + 1); CP_WAIT1(); }
    else            { CP_WAIT0(); }
    __syncthreads();
    const int bf = c & 1;
#pragma unroll
    for (int ks = 0; ks < 4; ++ks) {
      int kk = ks * 8;
      uint32_t af[2][4], bfr[8][2];
#pragma unroll
      for (int i = 0; i < 2; i++) {
        int mr = wm * 32 + i * 16;
        af[i][0] = __float_as_uint(As[bf][mr + group    ][kk + tg    ]);
        af[i][1] = __float_as_uint(As[bf][mr + group + 8][kk + tg    ]);
        af[i][2] = __float_as_uint(As[bf][mr + group    ][kk + tg + 4]);
        af[i][3] = __float_as_uint(As[bf][mr + group + 8][kk + tg + 4]);
      }
#pragma unroll
      for (int j = 0; j < 8; j++) {
        int nr = wn * 64 + j * 8;
        bfr[j][0] = __float_as_uint(Bs[bf][nr + group][kk + tg    ]);
        bfr[j][1] = __float_as_uint(Bs[bf][nr + group][kk + tg + 4]);
      }
#pragma unroll
      for (int i = 0; i < 2; i++)
#pragma unroll
        for (int j = 0; j < 8; j++)
          mma_tf32(acc[i][j], af[i], bfr[j]);
    }
    __syncthreads();
  }
#undef NT_LOAD
#pragma unroll
  for (int i = 0; i < 2; i++) {
    int row0 = m0 + wm * 32 + i * 16 + group;
#pragma unroll
    for (int j = 0; j < 8; j++) {
      int col = n0 + wn * 64 + j * 8 + tg * 2;
      if (col < N) {
        *(float2*)&C[(size_t)row0 * N + col]       = make_float2(acc[i][j][0], acc[i][j][1]);
        *(float2*)&C[(size_t)(row0 + 8) * N + col] = make_float2(acc[i][j][2], acc[i][j][3]);
      }
    }
  }
}

// ================= GEMM TN: C[M,N] = At^T @ B^T =================
// At is [K, lda] (m contiguous). A staged k-major, stride 136 (conflict-free).
#define TN_SMEM ((2*32*136 + 2*128*36)*4)
__global__ __launch_bounds__(256) void gemm_tn(const float* __restrict__ At,
    const float* __restrict__ B, float* __restrict__ C, int M, int N, int K,
    int lda, int sA, int sC) {
  At += (size_t)blockIdx.z * sA;
  C  += (size_t)blockIdx.z * sC;
  extern __shared__ float sm[];
  float (*Asr)[32][136] = (float(*)[32][136])sm;           // [buf][k][m]
  float (*Bs)[128][36]  = (float(*)[128][36])(sm + 2*32*136);
  const int tid = threadIdx.x;
  const int wid = tid >> 5, lane = tid & 31;
  const int wm = wid & 3, wn = wid >> 2;
  const int group = lane >> 2, tg = lane & 3;
  const int m0 = blockIdx.y * 128, n0 = blockIdx.x * 128;
  const int lr = tid >> 3, lk = tid & 7;
  const int akk = tid >> 3, amc = tid & 7;                 // A loader: k-row, m-chunk base
  const int KC = K / 32;

  float acc[2][8][4] = {};

#define TN_LOAD(c) do { \
    int k0 = (c) * 32; int bf_ = (c) & 1; \
    _Pragma("unroll") \
    for (int pass = 0; pass < 4; ++pass) { \
      int mc = amc + pass * 8; \
      cp16(&Asr[bf_][akk][mc*4], &At[(size_t)(k0 + akk)*lda + m0 + mc*4]); \
      int r = lr + pass * 32; \
      cp16z(&Bs[bf_][r][lk*4], &B[(size_t)(n0 + r)*K + k0 + lk*4], n0 + r < N); \
    } \
    CP_COMMIT(); \
  } while (0)

  TN_LOAD(0);
  for (int c = 0; c < KC; ++c) {
    if (c + 1 < KC) { TN_LOAD(c + 1); CP_WAIT1(); }
    else            { CP_WAIT0(); }
    __syncthreads();
    const int bf = c & 1;
#pragma unroll
    for (int ks = 0; ks < 4; ++ks) {
      int kk = ks * 8;
      uint32_t af[2][4], bfr[8][2];
#pragma unroll
      for (int i = 0; i < 2; i++) {
        int mr = wm * 32 + i * 16;
        af[i][0] = __float_as_uint(Asr[bf][kk + tg    ][mr + group    ]);
        af[i][1] = __float_as_uint(Asr[bf][kk + tg    ][mr + group + 8]);
        af[i][2] = __float_as_uint(Asr[bf][kk + tg + 4][mr + group    ]);
        af[i][3] = __float_as_uint(Asr[bf][kk + tg + 4][mr + group + 8]);
      }
#pragma unroll
      for (int j = 0; j < 8; j++) {
        int nr = wn * 64 + j * 8;
        bfr[j][0] = __float_as_uint(Bs[bf][nr + group][kk + tg    ]);
        bfr[j][1] = __float_as_uint(Bs[bf][nr + group][kk + tg + 4]);
      }
#pragma unroll
      for (int i = 0; i < 2; i++)
#pragma unroll
        for (int j = 0; j < 8; j++)
          mma_tf32(acc[i][j], af[i], bfr[j]);
    }
    __syncthreads();
  }
#undef TN_LOAD
#pragma unroll
  for (int i = 0; i < 2; i++) {
    int row0 = m0 + wm * 32 + i * 16 + group;
#pragma unroll
    for (int j = 0; j < 8; j++) {
      int col = n0 + wn * 64 + j * 8 + tg * 2;
      if (col < N) {
        *(float2*)&C[(size_t)row0 * N + col]       = make_float2(acc[i][j][0], acc[i][j][1]);
        *(float2*)&C[(size_t)(row0 + 8) * N + col] = make_float2(acc[i][j][2], acc[i][j][3]);
      }
    }
  }
}

// ================= conv + silu + z-silu, both transposed to [b,d,t] =================
__global__ void convz_kernel(const float* __restrict__ conv_w, const float* __restrict__ conv_b) {
  __shared__ float sx[67][33];
  __shared__ float sz[64][33];
  int b = blockIdx.z, t0 = blockIdx.x * 64, d0 = blockIdx.y * 32;
  int tid = threadIdx.y * 64 + threadIdx.x;
  for (int i = tid; i < 67*32; i += 256) {
    int r = i >> 5, c = i & 31;
    int t = t0 - 3 + r;
    sx[r][c] = (t >= 0) ? g_xz[(size_t)(b*SEQ + t)*2*DINNER + d0 + c] : 0.f;
  }
  for (int i = tid; i < 64*32; i += 256) {
    int r = i >> 5, c = i & 31;
    sz[r][c] = g_xz[(size_t)(b*SEQ + t0 + r)*2*DINNER + DINNER + d0 + c];
  }
  __syncthreads();
  int tx = threadIdx.x;
#pragma unroll
  for (int i = 0; i < 8; i++) {
    int dl = threadIdx.y * 8 + i;
    int d = d0 + dl;
    float w0 = conv_w[d*4+0], w1 = conv_w[d*4+1], w2 = conv_w[d*4+2], w3 = conv_w[d*4+3];
    float acc = conv_b[d];
    acc += sx[tx+0][dl]*w0 + sx[tx+1][dl]*w1 + sx[tx+2][dl]*w2 + sx[tx+3][dl]*w3;
    size_t o = (size_t)(b*DINNER + d)*SEQ + t0 + tx;
    g_ut[o] = siluf(acc);
    g_zt[o] = siluf(sz[tx][dl]);
  }
}

// ================= delta = softplus(dt @ W^T + b), transposed =================
__global__ void delta_kernel(const float* __restrict__ dtw, const float* __restrict__ dtb) {
  __shared__ float sdt[32][33];
  __shared__ float sw[32][33];
  int b = blockIdx.z, t0 = blockIdx.x * 32, d0 = blockIdx.y * 32;
  int tx = threadIdx.x, ty = threadIdx.y;
  int tid = ty * 32 + tx;
  for (int i = tid; i < 32*32; i += 256) {
    int q = i >> 5, r = i & 31;
    sdt[q][r] = g_dbc[(size_t)(b*SEQ + t0 + q)*DBC_W + r];
    sw[q][r]  = dtw[(d0 + q)*DTRANK + r];
  }
  __syncthreads();
#pragma unroll
  for (int i = 0; i < 4; i++) {
    int dl = ty * 4 + i;
    float acc = dtb[d0 + dl];
#pragma unroll
    for (int r = 0; r < 32; r++)
      acc = fmaf(sdt[tx][r], sw[dl][r], acc);
    g_deltat[(size_t)(b*DINNER + d0 + dl)*SEQ + t0 + tx] = softplusf(acc);
  }
}

// ================= selective scan: one warp per (b,d) =================
__global__ void scan_kernel(const float* __restrict__ Dw, const float* __restrict__ A_log) {
  int warp = threadIdx.x >> 5, lane = threadIdx.x & 31;
  int g = blockIdx.x * 8 + warp;
  int b = g >> 10, d = g & 1023;
  __shared__ float sBC[32][64];
  float An = -__expf(A_log[d*DSTATE + lane]);
  float Dd = Dw[d];
  float h = 0.f;
  const float* ut  = g_ut     + (size_t)(b*DINNER + d)*SEQ;
  const float* dtp = g_deltat + (size_t)(b*DINNER + d)*SEQ;
  const float* ztp = g_zt     + (size_t)(b*DINNER + d)*SEQ;
  float*       ytp = g_yt     + (size_t)(b*DINNER + d)*SEQ;

  for (int t0 = 0; t0 < SEQ; t0 += 32) {
    __syncthreads();
    for (int i = threadIdx.x; i < 32*64; i += 256) {
      int s = i >> 6, c = i & 63;
      sBC[s][c] = g_dbc[(size_t)(b*SEQ + t0 + s)*DBC_W + DSTATE + c];
    }
    __syncthreads();
    float du = ut[t0 + lane];
    float dd = dtp[t0 + lane];
    float sz = ztp[t0 + lane];
    float yreg = 0.f;
#pragma unroll 8
    for (int s = 0; s < 32; s++) {
      float delta_t = __shfl_sync(0xffffffffu, dd, s);
      float u_t     = __shfl_sync(0xffffffffu, du, s);
      float Bv = sBC[s][lane];
      float Cv = sBC[s][32 + lane];
      float dA = __expf(delta_t * An);
      h = fmaf(dA, h, delta_t * u_t * Bv);
      float pp = h * Cv;
      pp += __shfl_xor_sync(0xffffffffu, pp, 16);
      pp += __shfl_xor_sync(0xffffffffu, pp, 8);
      pp += __shfl_xor_sync(0xffffffffu, pp, 4);
      pp += __shfl_xor_sync(0xffffffffu, pp, 2);
      pp += __shfl_xor_sync(0xffffffffu, pp, 1);
      if (lane == s) yreg = (pp + du * Dd) * sz;
    }
    ytp[t0 + lane] = yreg;
  }
}

// ================= layernorm =================
__global__ void ln_kernel(const float* __restrict__ lnw, const float* __restrict__ lnb) {
  int row = blockIdx.x;
  const float* y = g_y2 + (size_t)row * DMODEL;
  float*       o = g_yn + (size_t)row * DMODEL;
  int tid = threadIdx.x;
  int lane = tid & 31, wid = tid >> 5;
  float v[4], s = 0.f, s2 = 0.f;
#pragma unroll
  for (int i = 0; i < 4; i++) {
    float x = y[tid + i*128];
    v[i] = x; s += x; s2 += x*x;
  }
#pragma unroll
  for (int off = 16; off >= 1; off >>= 1) {
    s  += __shfl_xor_sync(0xffffffffu, s, off);
    s2 += __shfl_xor_sync(0xffffffffu, s2, off);
  }
  __shared__ float sh[10];
  if (lane == 0) { sh[wid] = s; sh[4 + wid] = s2; }
  __syncthreads();
  if (tid == 0) {
    float ts = sh[0] + sh[1] + sh[2] + sh[3];
    float ts2 = sh[4] + sh[5] + sh[6] + sh[7];
    float mu = ts * (1.f/DMODEL);
    float var = ts2 * (1.f/DMODEL) - mu*mu;
    sh[8] = mu;
    sh[9] = rsqrtf(var + 1e-5f);
  }
  __syncthreads();
  float mu = sh[8], inv = sh[9];
#pragma unroll
  for (int i = 0; i < 4; i++) {
    int c = tid + i*128;
    o[c] = (v[i] - mu) * inv * lnw[c] + lnb[c];
  }
}

// ================= gelu + bias + residual(tokens) + inverse-perm scatter =================
__global__ void final_kernel(const float* __restrict__ lin_b,
                             const float* __restrict__ tokens, float* __restrict__ out) {
  int e = blockIdx.x * 256 + threadIdx.x;
  int c  = e & (DMODEL - 1);
  int bp = e >> 9;
  int b  = bp >> 10, p = bp & (SEQ - 1);
  int src = perm_src(p);
  float x = g_lin[e] + lin_b[c];
  float gl = 0.5f * x * (1.f + erff(x * 0.70710678118654752f));
  size_t oidx = (size_t)(b*SEQ + src)*DMODEL + c;
  out[oidx] = gl + tokens[oidx];
}

// ================= launch =================
extern "C" void kernel_launch(void* const* d_in, const int* in_sizes, int n_in,
                              void* d_out, int out_size) {
  const float* tokens     = (const float*)d_in[0];
  const float* in_proj_w  = (const float*)d_in[1];
  const float* conv_w     = (const float*)d_in[2];
  const float* conv_b     = (const float*)d_in[3];
  const float* x_proj_w   = (const float*)d_in[4];
  const float* dt_proj_w  = (const float*)d_in[5];
  const float* dt_proj_b  = (const float*)d_in[6];
  const float* A_log      = (const float*)d_in[7];
  const float* Dw         = (const float*)d_in[8];
  const float* out_proj_w = (const float*)d_in[9];
  const float* ln_w       = (const float*)d_in[10];
  const float* ln_b       = (const float*)d_in[11];
  const float* lin_w      = (const float*)d_in[12];
  const float* lin_b      = (const float*)d_in[13];
  float* out = (float*)d_out;

  float *p_xz, *p_ut, *p_dbc, *p_yt, *p_y2, *p_yn, *p_lin;
  cudaGetSymbolAddress((void**)&p_xz,    g_xz);
  cudaGetSymbolAddress((void**)&p_ut,    g_ut);
  cudaGetSymbolAddress((void**)&p_dbc,   g_dbc);
  cudaGetSymbolAddress((void**)&p_yt,    g_yt);
  cudaGetSymbolAddress((void**)&p_y2,    g_y2);
  cudaGetSymbolAddress((void**)&p_yn,    g_yn);
  cudaGetSymbolAddress((void**)&p_lin,   g_lin);

  cudaFuncSetAttribute(gemm_nt, cudaFuncAttributeMaxDynamicSharedMemorySize, NT_SMEM);
  cudaFuncSetAttribute(gemm_tn, cudaFuncAttributeMaxDynamicSharedMemorySize, TN_SMEM);

  // 1. xz = perm(tokens) @ in_proj_w^T   [4096 x 2048 x 512], permutation fused in A-gather
  gemm_nt<<<dim3(2*DINNER/128, NROWS/128), 256, NT_SMEM>>>(tokens, in_proj_w, p_xz,
                                                           NROWS, 2*DINNER, DMODEL, 1);
  // 2. conv+silu -> ut ; silu(z) -> zt   (fused, both [b,d,t])
  convz_kernel<<<dim3(SEQ/64, DINNER/32, BATCH), dim3(64,4)>>>(conv_w, conv_b);
  // 3. dbc = u @ x_proj_w^T   [per-b: 1024 x 96 x 1024]
  gemm_tn<<<dim3(1, SEQ/128, BATCH), 256, TN_SMEM>>>(p_ut, x_proj_w, p_dbc,
                                                     SEQ, DBC_W, DINNER,
                                                     SEQ, DINNER*SEQ, SEQ*DBC_W);
  // 4. delta
  delta_kernel<<<dim3(SEQ/32, DINNER/32, BATCH), dim3(32,8)>>>(dt_proj_w, dt_proj_b);
  // 5. scan -> yt[b,d,t]
  scan_kernel<<<NROWS/8, 256>>>(Dw, A_log);
  // 6. y2 = y @ out_proj_w^T  [per-b: 1024 x 512 x 1024]
  gemm_tn<<<dim3(DMODEL/128, SEQ/128, BATCH), 256, TN_SMEM>>>(p_yt, out_proj_w, p_y2,
                                                              SEQ, DMODEL, DINNER,
                                                              SEQ, DINNER*SEQ, SEQ*DMODEL);
  // 7. layernorm
  ln_kernel<<<NROWS, 128>>>(ln_w, ln_b);
  // 8. lin = yn @ lin_w^T  [4096 x 512 x 512]
  gemm_nt<<<dim3(DMODEL/128, NROWS/128), 256, NT_SMEM>>>(p_yn, lin_w, p_lin,
                                                         NROWS, DMODEL, DMODEL, 0);
  // 9. gelu + bias + residual + inverse-permute scatter
  final_kernel<<<NROWS*DMODEL/256, 256>>>(lin_b, tokens, out);
}

// round 5
// speedup vs baseline: 2.2222x; 1.1112x over previous
#include <cuda_runtime.h>
#include <cstdint>
#include <math.h>

#define BATCH  4
#define SEQ    1024
#define DMODEL 512
#define DINNER 1024
#define DSTATE 32
#define DTRANK 32
#define DBC_W  96
#define NROWS  (BATCH*SEQ)   // 4096

// ================= scratch =================
__device__ float g_xz    [BATCH*SEQ*2*DINNER];
__device__ float g_ut    [BATCH*DINNER*SEQ];
__device__ float g_zt    [BATCH*DINNER*SEQ];
__device__ float g_dbc   [BATCH*SEQ*DBC_W];
__device__ float g_deltat[BATCH*DINNER*SEQ];
__device__ float g_yt    [BATCH*DINNER*SEQ];
__device__ float g_y2    [BATCH*SEQ*DMODEL];
__device__ float g_yn    [BATCH*SEQ*DMODEL];

__device__ __forceinline__ int perm_src(int p) {
  int r = p >> 5, c = p & 31;
  if (r & 1) c = 31 - c;
  return (r << 5) | c;
}
__device__ __forceinline__ int remap_row(int m) {   // (b,p) -> b*SEQ + perm[p]
  return (m & ~(SEQ - 1)) + perm_src(m & (SEQ - 1));
}
__device__ __forceinline__ float softplusf(float x) {
  return fmaxf(x, 0.f) + log1pf(expf(-fabsf(x)));
}
__device__ __forceinline__ float siluf(float x) {
  return x / (1.f + expf(-x));
}
__device__ __forceinline__ float geluf(float x) {
  return 0.5f * x * (1.f + erff(x * 0.70710678118654752f));
}
__device__ __forceinline__ uint32_t smem_u32(const void* p) {
  uint32_t a;
  asm("{ .reg .u64 t; cvta.to.shared.u64 t, %1; cvt.u32.u64 %0, t; }" : "=r"(a) : "l"(p));
  return a;
}
__device__ __forceinline__ void cp16(void* dst, const void* src) {
  asm volatile("cp.async.cg.shared.global [%0], [%1], 16;"
               :: "r"(smem_u32(dst)), "l"(src));
}
__device__ __forceinline__ void cp16z(void* dst, const void* src, bool valid) {
  int sz = valid ? 16 : 0;
  asm volatile("cp.async.cg.shared.global [%0], [%1], 16, %2;"
               :: "r"(smem_u32(dst)), "l"(src), "r"(sz));
}
#define CP_COMMIT() asm volatile("cp.async.commit_group;" ::: "memory")
#define CP_WAIT1()  asm volatile("cp.async.wait_group 1;" ::: "memory")
#define CP_WAIT0()  asm volatile("cp.async.wait_group 0;" ::: "memory")

__device__ __forceinline__ void mma_tf32(float* c, const uint32_t* a, const uint32_t* b) {
  asm volatile(
    "mma.sync.aligned.m16n8k8.row.col.f32.tf32.tf32.f32 "
    "{%0,%1,%2,%3}, {%4,%5,%6,%7}, {%8,%9}, {%0,%1,%2,%3};"
    : "+f"(c[0]), "+f"(c[1]), "+f"(c[2]), "+f"(c[3])
    : "r"(a[0]), "r"(a[1]), "r"(a[2]), "r"(a[3]), "r"(b[0]), "r"(b[1]));
}

// ================= GEMM NT: C[M,N] = A[M,K] @ B[N,K]^T =================
// 128x128x32 tiles, 8 warps (4M x 2N), warp tile 32x64, cp.async 2-stage.
// gatherA: A rows pass through remap_row. epi=1: gelu+bias+residual, rows
// scatter through remap_row (fused final stage of the block).
#define NT_SMEM (2*128*36*2*4)
__global__ __launch_bounds__(256) void gemm_nt(const float* __restrict__ A,
    const float* __restrict__ B, float* __restrict__ C, int M, int N, int K,
    int gatherA, int epi, const float* __restrict__ bias,
    const float* __restrict__ resid) {
  extern __shared__ float sm[];
  float (*As)[128][36] = (float(*)[128][36])sm;
  float (*Bs)[128][36] = (float(*)[128][36])(sm + 2*128*36);
  const int tid = threadIdx.x;
  const int wid = tid >> 5, lane = tid & 31;
  const int wm = wid & 3, wn = wid >> 2;
  const int group = lane >> 2, tg = lane & 3;
  const int m0 = blockIdx.y * 128, n0 = blockIdx.x * 128;
  const int lr = tid >> 3, lk = tid & 7;
  const int KC = K / 32;

  float acc[2][8][4] = {};

  int arow[4];
#pragma unroll
  for (int pass = 0; pass < 4; ++pass) {
    int m = m0 + lr + pass * 32;
    arow[pass] = gatherA ? remap_row(m) : m;
  }

#define NT_LOAD(c) do { \
    int k0 = (c) * 32; int bf_ = (c) & 1; \
    _Pragma("unroll") \
    for (int pass = 0; pass < 4; ++pass) { \
      int r = lr + pass * 32; \
      cp16(&As[bf_][r][lk*4], &A[(size_t)arow[pass]*K + k0 + lk*4]); \
      cp16z(&Bs[bf_][r][lk*4], &B[(size_t)(n0 + r)*K + k0 + lk*4], n0 + r < N); \
    } \
    CP_COMMIT(); \
  } while (0)

  NT_LOAD(0);
  for (int c = 0; c < KC; ++c) {
    if (c + 1 < KC) { NT_LOAD(c + 1); CP_WAIT1(); }
    else            { CP_WAIT0(); }
    __syncthreads();
    const int bf = c & 1;
#pragma unroll
    for (int ks = 0; ks < 4; ++ks) {
      int kk = ks * 8;
      uint32_t af[2][4], bfr[8][2];
#pragma unroll
      for (int i = 0; i < 2; i++) {
        int mr = wm * 32 + i * 16;
        af[i][0] = __float_as_uint(As[bf][mr + group    ][kk + tg    ]);
        af[i][1] = __float_as_uint(As[bf][mr + group + 8][kk + tg    ]);
        af[i][2] = __float_as_uint(As[bf][mr + group    ][kk + tg + 4]);
        af[i][3] = __float_as_uint(As[bf][mr + group + 8][kk + tg + 4]);
      }
#pragma unroll
      for (int j = 0; j < 8; j++) {
        int nr = wn * 64 + j * 8;
        bfr[j][0] = __float_as_uint(Bs[bf][nr + group][kk + tg    ]);
        bfr[j][1] = __float_as_uint(Bs[bf][nr + group][kk + tg + 4]);
      }
#pragma unroll
      for (int i = 0; i < 2; i++)
#pragma unroll
        for (int j = 0; j < 8; j++)
          mma_tf32(acc[i][j], af[i], bfr[j]);
    }
    __syncthreads();
  }
#undef NT_LOAD
  if (epi == 0) {
#pragma unroll
    for (int i = 0; i < 2; i++) {
      int row0 = m0 + wm * 32 + i * 16 + group;
#pragma unroll
      for (int j = 0; j < 8; j++) {
        int col = n0 + wn * 64 + j * 8 + tg * 2;
        if (col < N) {
          *(float2*)&C[(size_t)row0 * N + col]       = make_float2(acc[i][j][0], acc[i][j][1]);
          *(float2*)&C[(size_t)(row0 + 8) * N + col] = make_float2(acc[i][j][2], acc[i][j][3]);
        }
      }
    }
  } else {
#pragma unroll
    for (int i = 0; i < 2; i++) {
      int row0 = m0 + wm * 32 + i * 16 + group;
      int ra = remap_row(row0), rb = remap_row(row0 + 8);
#pragma unroll
      for (int j = 0; j < 8; j++) {
        int col = n0 + wn * 64 + j * 8 + tg * 2;
        float b0 = bias[col], b1 = bias[col + 1];
        size_t oa = (size_t)ra * N + col, ob = (size_t)rb * N + col;
        float2 r0 = *(const float2*)&resid[oa];
        float2 r1 = *(const float2*)&resid[ob];
        *(float2*)&C[oa] = make_float2(geluf(acc[i][j][0] + b0) + r0.x,
                                       geluf(acc[i][j][1] + b1) + r0.y);
        *(float2*)&C[ob] = make_float2(geluf(acc[i][j][2] + b0) + r1.x,
                                       geluf(acc[i][j][3] + b1) + r1.y);
      }
    }
  }
}

// ================= GEMM TN: C[M,N] = At^T @ B^T =================
// At is [K, lda] (m contiguous). A staged k-major, stride 136 (conflict-free).
#define TN_SMEM ((2*32*136 + 2*128*36)*4)
__global__ __launch_bounds__(256) void gemm_tn(const float* __restrict__ At,
    const float* __restrict__ B, float* __restrict__ C, int M, int N, int K,
    int lda, int sA, int sC) {
  At += (size_t)blockIdx.z * sA;
  C  += (size_t)blockIdx.z * sC;
  extern __shared__ float sm[];
  float (*Asr)[32][136] = (float(*)[32][136])sm;           // [buf][k][m]
  float (*Bs)[128][36]  = (float(*)[128][36])(sm + 2*32*136);
  const int tid = threadIdx.x;
  const int wid = tid >> 5, lane = tid & 31;
  const int wm = wid & 3, wn = wid >> 2;
  const int group = lane >> 2, tg = lane & 3;
  const int m0 = blockIdx.y * 128, n0 = blockIdx.x * 128;
  const int lr = tid >> 3, lk = tid & 7;
  const int akk = tid >> 3, amc = tid & 7;
  const int KC = K / 32;

  float acc[2][8][4] = {};

#define TN_LOAD(c) do { \
    int k0 = (c) * 32; int bf_ = (c) & 1; \
    _Pragma("unroll") \
    for (int pass = 0; pass < 4; ++pass) { \
      int mc = amc + pass * 8; \
      cp16(&Asr[bf_][akk][mc*4], &At[(size_t)(k0 + akk)*lda + m0 + mc*4]); \
      int r = lr + pass * 32; \
      cp16z(&Bs[bf_][r][lk*4], &B[(size_t)(n0 + r)*K + k0 + lk*4], n0 + r < N); \
    } \
    CP_COMMIT(); \
  } while (0)

  TN_LOAD(0);
  for (int c = 0; c < KC; ++c) {
    if (c + 1 < KC) { TN_LOAD(c + 1); CP_WAIT1(); }
    else            { CP_WAIT0(); }
    __syncthreads();
    const int bf = c & 1;
#pragma unroll
    for (int ks = 0; ks < 4; ++ks) {
      int kk = ks * 8;
      uint32_t af[2][4], bfr[8][2];
#pragma unroll
      for (int i = 0; i < 2; i++) {
        int mr = wm * 32 + i * 16;
        af[i][0] = __float_as_uint(Asr[bf][kk + tg    ][mr + group    ]);
        af[i][1] = __float_as_uint(Asr[bf][kk + tg    ][mr + group + 8]);
        af[i][2] = __float_as_uint(Asr[bf][kk + tg + 4][mr + group    ]);
        af[i][3] = __float_as_uint(Asr[bf][kk + tg + 4][mr + group + 8]);
      }
#pragma unroll
      for (int j = 0; j < 8; j++) {
        int nr = wn * 64 + j * 8;
        bfr[j][0] = __float_as_uint(Bs[bf][nr + group][kk + tg    ]);
        bfr[j][1] = __float_as_uint(Bs[bf][nr + group][kk + tg + 4]);
      }
#pragma unroll
      for (int i = 0; i < 2; i++)
#pragma unroll
        for (int j = 0; j < 8; j++)
          mma_tf32(acc[i][j], af[i], bfr[j]);
    }
    __syncthreads();
  }
#undef TN_LOAD
#pragma unroll
  for (int i = 0; i < 2; i++) {
    int row0 = m0 + wm * 32 + i * 16 + group;
#pragma unroll
    for (int j = 0; j < 8; j++) {
      int col = n0 + wn * 64 + j * 8 + tg * 2;
      if (col < N) {
        *(float2*)&C[(size_t)row0 * N + col]       = make_float2(acc[i][j][0], acc[i][j][1]);
        *(float2*)&C[(size_t)(row0 + 8) * N + col] = make_float2(acc[i][j][2], acc[i][j][3]);
      }
    }
  }
}

// ================= delta via mma: deltat[b,d,t] = softplus(W[d]·dt[b,t] + bias[d]) ===
// A = dt_proj_w [DINNER,32] row-major; B = dbc rows (ld=96, first 32 cols).
__global__ __launch_bounds__(256) void delta_mma(const float* __restrict__ W,
    const float* __restrict__ dbc, const float* __restrict__ bias,
    float* __restrict__ outp) {
  __shared__ float As[128][36];
  __shared__ float Bs[128][36];
  const int b = blockIdx.z;
  const int tid = threadIdx.x;
  const int wid = tid >> 5, lane = tid & 31;
  const int wm = wid & 3, wn = wid >> 2;
  const int group = lane >> 2, tg = lane & 3;
  const int m0 = blockIdx.y * 128, n0 = blockIdx.x * 128;   // m = d, n = t

  const float* Bb = dbc + (size_t)b * SEQ * DBC_W;
#pragma unroll
  for (int pass = 0; pass < 4; ++pass) {
    int i = tid + pass * 256;
    int r = i >> 3, q = i & 7;
    if (q < 8) {
      *(float4*)&As[r][q * 4] = *(const float4*)&W[(size_t)(m0 + r) * DTRANK + q * 4];
      *(float4*)&Bs[r][q * 4] = *(const float4*)&Bb[(size_t)(n0 + r) * DBC_W + q * 4];
    }
  }
  __syncthreads();

  float acc[2][8][4] = {};
#pragma unroll
  for (int ks = 0; ks < 4; ++ks) {
    int kk = ks * 8;
    uint32_t af[2][4], bfr[8][2];
#pragma unroll
    for (int i = 0; i < 2; i++) {
      int mr = wm * 32 + i * 16;
      af[i][0] = __float_as_uint(As[mr + group    ][kk + tg    ]);
      af[i][1] = __float_as_uint(As[mr + group + 8][kk + tg    ]);
      af[i][2] = __float_as_uint(As[mr + group    ][kk + tg + 4]);
      af[i][3] = __float_as_uint(As[mr + group + 8][kk + tg + 4]);
    }
#pragma unroll
    for (int j = 0; j < 8; j++) {
      int nr = wn * 64 + j * 8;
      bfr[j][0] = __float_as_uint(Bs[nr + group][kk + tg    ]);
      bfr[j][1] = __float_as_uint(Bs[nr + group][kk + tg + 4]);
    }
#pragma unroll
    for (int i = 0; i < 2; i++)
#pragma unroll
      for (int j = 0; j < 8; j++)
        mma_tf32(acc[i][j], af[i], bfr[j]);
  }
  // epilogue: softplus(acc + bias[d]) -> outp[(b*DINNER + d)*SEQ + t]
  float* ob = outp + (size_t)b * DINNER * SEQ;
#pragma unroll
  for (int i = 0; i < 2; i++) {
    int d0 = m0 + wm * 32 + i * 16 + group;
    float ba = bias[d0], bb2 = bias[d0 + 8];
#pragma unroll
    for (int j = 0; j < 8; j++) {
      int t = n0 + wn * 64 + j * 8 + tg * 2;
      *(float2*)&ob[(size_t)d0 * SEQ + t] =
        make_float2(softplusf(acc[i][j][0] + ba), softplusf(acc[i][j][1] + ba));
      *(float2*)&ob[(size_t)(d0 + 8) * SEQ + t] =
        make_float2(softplusf(acc[i][j][2] + bb2), softplusf(acc[i][j][3] + bb2));
    }
  }
}

// ================= conv + silu + z-silu, both transposed to [b,d,t] =================
__global__ void convz_kernel(const float* __restrict__ conv_w, const float* __restrict__ conv_b) {
  __shared__ float sx[67][33];
  __shared__ float sz[64][33];
  int b = blockIdx.z, t0 = blockIdx.x * 64, d0 = blockIdx.y * 32;
  int tid = threadIdx.y * 64 + threadIdx.x;
  for (int i = tid; i < 67*32; i += 256) {
    int r = i >> 5, c = i & 31;
    int t = t0 - 3 + r;
    sx[r][c] = (t >= 0) ? g_xz[(size_t)(b*SEQ + t)*2*DINNER + d0 + c] : 0.f;
  }
  for (int i = tid; i < 64*32; i += 256) {
    int r = i >> 5, c = i & 31;
    sz[r][c] = g_xz[(size_t)(b*SEQ + t0 + r)*2*DINNER + DINNER + d0 + c];
  }
  __syncthreads();
  int tx = threadIdx.x;
#pragma unroll
  for (int i = 0; i < 8; i++) {
    int dl = threadIdx.y * 8 + i;
    int d = d0 + dl;
    float w0 = conv_w[d*4+0], w1 = conv_w[d*4+1], w2 = conv_w[d*4+2], w3 = conv_w[d*4+3];
    float acc = conv_b[d];
    acc += sx[tx+0][dl]*w0 + sx[tx+1][dl]*w1 + sx[tx+2][dl]*w2 + sx[tx+3][dl]*w3;
    size_t o = (size_t)(b*DINNER + d)*SEQ + t0 + tx;
    g_ut[o] = siluf(acc);
    g_zt[o] = siluf(sz[tx][dl]);
  }
}

// ================= selective scan: one warp per (b,d), deferred reduction =========
__global__ void scan_kernel(const float* __restrict__ Dw, const float* __restrict__ A_log) {
  int warp = threadIdx.x >> 5, lane = threadIdx.x & 31;
  int g = blockIdx.x * 8 + warp;
  int b = g >> 10, d = g & 1023;
  __shared__ float sBC[32][64];
  __shared__ float sP[8][32][34];
  float An = -__expf(A_log[d*DSTATE + lane]);
  float Dd = Dw[d];
  float h = 0.f;
  const float* ut  = g_ut     + (size_t)(b*DINNER + d)*SEQ;
  const float* dtp = g_deltat + (size_t)(b*DINNER + d)*SEQ;
  const float* ztp = g_zt     + (size_t)(b*DINNER + d)*SEQ;
  float*       ytp = g_yt     + (size_t)(b*DINNER + d)*SEQ;

  for (int t0 = 0; t0 < SEQ; t0 += 32) {
    __syncthreads();
    for (int i = threadIdx.x; i < 32*64; i += 256) {
      int s = i >> 6, c = i & 63;
      sBC[s][c] = g_dbc[(size_t)(b*SEQ + t0 + s)*DBC_W + DSTATE + c];
    }
    __syncthreads();
    float du = ut[t0 + lane];
    float dd = dtp[t0 + lane];
    float sz = ztp[t0 + lane];
#pragma unroll 8
    for (int s = 0; s < 32; s++) {
      float delta_t = __shfl_sync(0xffffffffu, dd, s);
      float u_t     = __shfl_sync(0xffffffffu, du, s);
      float dA = __expf(delta_t * An);
      h = fmaf(dA, h, delta_t * u_t * sBC[s][lane]);
      sP[warp][s][lane] = h * sBC[s][32 + lane];
    }
    __syncwarp();
    float y = du * Dd;
#pragma unroll
    for (int i = 0; i < 32; i++) {
      int c = (lane + i) & 31;
      y += sP[warp][lane][c];
    }
    ytp[t0 + lane] = y * sz;
  }
}

// ================= layernorm =================
__global__ void ln_kernel(const float* __restrict__ lnw, const float* __restrict__ lnb) {
  int row = blockIdx.x;
  const float* y = g_y2 + (size_t)row * DMODEL;
  float*       o = g_yn + (size_t)row * DMODEL;
  int tid = threadIdx.x;
  int lane = tid & 31, wid = tid >> 5;
  float v[4], s = 0.f, s2 = 0.f;
#pragma unroll
  for (int i = 0; i < 4; i++) {
    float x = y[tid + i*128];
    v[i] = x; s += x; s2 += x*x;
  }
#pragma unroll
  for (int off = 16; off >= 1; off >>= 1) {
    s  += __shfl_xor_sync(0xffffffffu, s, off);
    s2 += __shfl_xor_sync(0xffffffffu, s2, off);
  }
  __shared__ float sh[10];
  if (lane == 0) { sh[wid] = s; sh[4 + wid] = s2; }
  __syncthreads();
  if (tid == 0) {
    float ts = sh[0] + sh[1] + sh[2] + sh[3];
    float ts2 = sh[4] + sh[5] + sh[6] + sh[7];
    float mu = ts * (1.f/DMODEL);
    float var = ts2 * (1.f/DMODEL) - mu*mu;
    sh[8] = mu;
    sh[9] = rsqrtf(var + 1e-5f);
  }
  __syncthreads();
  float mu = sh[8], inv = sh[9];
#pragma unroll
  for (int i = 0; i < 4; i++) {
    int c = tid + i*128;
    o[c] = (v[i] - mu) * inv * lnw[c] + lnb[c];
  }
}

// ================= launch =================
extern "C" void kernel_launch(void* const* d_in, const int* in_sizes, int n_in,
                              void* d_out, int out_size) {
  const float* tokens     = (const float*)d_in[0];
  const float* in_proj_w  = (const float*)d_in[1];
  const float* conv_w     = (const float*)d_in[2];
  const float* conv_b     = (const float*)d_in[3];
  const float* x_proj_w   = (const float*)d_in[4];
  const float* dt_proj_w  = (const float*)d_in[5];
  const float* dt_proj_b  = (const float*)d_in[6];
  const float* A_log      = (const float*)d_in[7];
  const float* Dw         = (const float*)d_in[8];
  const float* out_proj_w = (const float*)d_in[9];
  const float* ln_w       = (const float*)d_in[10];
  const float* ln_b       = (const float*)d_in[11];
  const float* lin_w      = (const float*)d_in[12];
  const float* lin_b      = (const float*)d_in[13];
  float* out = (float*)d_out;

  float *p_xz, *p_ut, *p_dbc, *p_deltat, *p_yt, *p_y2, *p_yn;
  cudaGetSymbolAddress((void**)&p_xz,     g_xz);
  cudaGetSymbolAddress((void**)&p_ut,     g_ut);
  cudaGetSymbolAddress((void**)&p_dbc,    g_dbc);
  cudaGetSymbolAddress((void**)&p_deltat, g_deltat);
  cudaGetSymbolAddress((void**)&p_yt,     g_yt);
  cudaGetSymbolAddress((void**)&p_y2,     g_y2);
  cudaGetSymbolAddress((void**)&p_yn,     g_yn);

  cudaFuncSetAttribute(gemm_nt, cudaFuncAttributeMaxDynamicSharedMemorySize, NT_SMEM);
  cudaFuncSetAttribute(gemm_tn, cudaFuncAttributeMaxDynamicSharedMemorySize, TN_SMEM);

  // 1. xz = perm(tokens) @ in_proj_w^T   [4096 x 2048 x 512]
  gemm_nt<<<dim3(2*DINNER/128, NROWS/128), 256, NT_SMEM>>>(tokens, in_proj_w, p_xz,
                                                           NROWS, 2*DINNER, DMODEL,
                                                           1, 0, nullptr, nullptr);
  // 2. conv+silu -> ut ; silu(z) -> zt   (fused, both [b,d,t])
  convz_kernel<<<dim3(SEQ/64, DINNER/32, BATCH), dim3(64,4)>>>(conv_w, conv_b);
  // 3. dbc = u @ x_proj_w^T   [per-b: 1024 x 96 x 1024]
  gemm_tn<<<dim3(1, SEQ/128, BATCH), 256, TN_SMEM>>>(p_ut, x_proj_w, p_dbc,
                                                     SEQ, DBC_W, DINNER,
                                                     SEQ, DINNER*SEQ, SEQ*DBC_W);
  // 4. delta = softplus(dt @ W^T + b) -> [b,d,t]   (mma)
  delta_mma<<<dim3(SEQ/128, DINNER/128, BATCH), 256>>>(dt_proj_w, p_dbc, dt_proj_b, p_deltat);
  // 5. scan -> yt[b,d,t]
  scan_kernel<<<NROWS/8, 256>>>(Dw, A_log);
  // 6. y2 = y @ out_proj_w^T  [per-b: 1024 x 512 x 1024]
  gemm_tn<<<dim3(DMODEL/128, SEQ/128, BATCH), 256, TN_SMEM>>>(p_yt, out_proj_w, p_y2,
                                                              SEQ, DMODEL, DINNER,
                                                              SEQ, DINNER*SEQ, SEQ*DMODEL);
  // 7. layernorm
  ln_kernel<<<NROWS, 128>>>(ln_w, ln_b);
  // 8. out = gelu(yn @ lin_w^T + lin_b) + residual, inverse-perm scatter (fused epi)
  gemm_nt<<<dim3(DMODEL/128, NROWS/128), 256, NT_SMEM>>>(p_yn, lin_w, out,
                                                         NROWS, DMODEL, DMODEL,
                                                         0, 1, lin_b, tokens);
}

// round 6
// speedup vs baseline: 2.4334x; 1.0951x over previous
#include <cuda_runtime.h>
#include <cstdint>
#include <math.h>

#define BATCH  4
#define SEQ    1024
#define DMODEL 512
#define DINNER 1024
#define DSTATE 32
#define DTRANK 32
#define DBC_W  96
#define NROWS  (BATCH*SEQ)   // 4096
#define XSPLIT 4             // split-K factor for x_proj

// ================= scratch =================
__device__ float g_xz    [BATCH*SEQ*2*DINNER];
__device__ float g_ut    [BATCH*DINNER*SEQ];
__device__ float g_zt    [BATCH*DINNER*SEQ];
__device__ float g_dbcp  [XSPLIT*BATCH*SEQ*DBC_W];   // split-K partials
__device__ float g_dbc   [BATCH*SEQ*DBC_W];
__device__ float g_deltat[BATCH*DINNER*SEQ];
__device__ float g_yt    [BATCH*DINNER*SEQ];
__device__ float g_y2    [BATCH*SEQ*DMODEL];
__device__ float g_yn    [BATCH*SEQ*DMODEL];

__device__ __forceinline__ int perm_src(int p) {
  int r = p >> 5, c = p & 31;
  if (r & 1) c = 31 - c;
  return (r << 5) | c;
}
__device__ __forceinline__ int remap_row(int m) {
  return (m & ~(SEQ - 1)) + perm_src(m & (SEQ - 1));
}
__device__ __forceinline__ float softplusf(float x) {
  return fmaxf(x, 0.f) + __logf(1.f + __expf(-fabsf(x)));
}
__device__ __forceinline__ float siluf(float x) {
  return __fdividef(x, 1.f + __expf(-x));
}
__device__ __forceinline__ float fast_erff(float x) {
  // Abramowitz-Stegun 7.1.26, |eps| <= 1.5e-7
  float ax = fabsf(x);
  float t = __frcp_rn(fmaf(0.3275911f, ax, 1.f));
  float p = t * fmaf(t, fmaf(t, fmaf(t, fmaf(t, 1.061405429f, -1.453152027f),
                     1.421413741f), -0.284496736f), 0.254829592f);
  float r = 1.f - p * __expf(-ax * ax);
  return copysignf(r, x);
}
__device__ __forceinline__ float geluf(float x) {
  return 0.5f * x * (1.f + fast_erff(x * 0.70710678118654752f));
}
__device__ __forceinline__ uint32_t smem_u32(const void* p) {
  uint32_t a;
  asm("{ .reg .u64 t; cvta.to.shared.u64 t, %1; cvt.u32.u64 %0, t; }" : "=r"(a) : "l"(p));
  return a;
}
__device__ __forceinline__ void cp16(void* dst, const void* src) {
  asm volatile("cp.async.cg.shared.global [%0], [%1], 16;"
               :: "r"(smem_u32(dst)), "l"(src));
}
__device__ __forceinline__ void cp16z(void* dst, const void* src, bool valid) {
  int sz = valid ? 16 : 0;
  asm volatile("cp.async.cg.shared.global [%0], [%1], 16, %2;"
               :: "r"(smem_u32(dst)), "l"(src), "r"(sz));
}
#define CP_COMMIT() asm volatile("cp.async.commit_group;" ::: "memory")
#define CP_WAIT1()  asm volatile("cp.async.wait_group 1;" ::: "memory")
#define CP_WAIT0()  asm volatile("cp.async.wait_group 0;" ::: "memory")

__device__ __forceinline__ void mma_tf32(float* c, const uint32_t* a, const uint32_t* b) {
  asm volatile(
    "mma.sync.aligned.m16n8k8.row.col.f32.tf32.tf32.f32 "
    "{%0,%1,%2,%3}, {%4,%5,%6,%7}, {%8,%9}, {%0,%1,%2,%3};"
    : "+f"(c[0]), "+f"(c[1]), "+f"(c[2]), "+f"(c[3])
    : "r"(a[0]), "r"(a[1]), "r"(a[2]), "r"(a[3]), "r"(b[0]), "r"(b[1]));
}

// ================= GEMM NT: C[M,N] = A[M,K] @ B[N,K]^T =================
#define NT_SMEM (2*128*36*2*4)
__global__ __launch_bounds__(256) void gemm_nt(const float* __restrict__ A,
    const float* __restrict__ B, float* __restrict__ C, int M, int N, int K,
    int gatherA, int epi, const float* __restrict__ bias,
    const float* __restrict__ resid) {
  extern __shared__ float sm[];
  float (*As)[128][36] = (float(*)[128][36])sm;
  float (*Bs)[128][36] = (float(*)[128][36])(sm + 2*128*36);
  const int tid = threadIdx.x;
  const int wid = tid >> 5, lane = tid & 31;
  const int wm = wid & 3, wn = wid >> 2;
  const int group = lane >> 2, tg = lane & 3;
  const int m0 = blockIdx.y * 128, n0 = blockIdx.x * 128;
  const int lr = tid >> 3, lk = tid & 7;
  const int KC = K / 32;

  float acc[2][8][4] = {};

  int arow[4];
#pragma unroll
  for (int pass = 0; pass < 4; ++pass) {
    int m = m0 + lr + pass * 32;
    arow[pass] = gatherA ? remap_row(m) : m;
  }

#define NT_LOAD(c) do { \
    int k0 = (c) * 32; int bf_ = (c) & 1; \
    _Pragma("unroll") \
    for (int pass = 0; pass < 4; ++pass) { \
      int r = lr + pass * 32; \
      cp16(&As[bf_][r][lk*4], &A[(size_t)arow[pass]*K + k0 + lk*4]); \
      cp16z(&Bs[bf_][r][lk*4], &B[(size_t)(n0 + r)*K + k0 + lk*4], n0 + r < N); \
    } \
    CP_COMMIT(); \
  } while (0)

  NT_LOAD(0);
  for (int c = 0; c < KC; ++c) {
    if (c + 1 < KC) { NT_LOAD(c + 1); CP_WAIT1(); }
    else            { CP_WAIT0(); }
    __syncthreads();
    const int bf = c & 1;
#pragma unroll
    for (int ks = 0; ks < 4; ++ks) {
      int kk = ks * 8;
      uint32_t af[2][4], bfr[8][2];
#pragma unroll
      for (int i = 0; i < 2; i++) {
        int mr = wm * 32 + i * 16;
        af[i][0] = __float_as_uint(As[bf][mr + group    ][kk + tg    ]);
        af[i][1] = __float_as_uint(As[bf][mr + group + 8][kk + tg    ]);
        af[i][2] = __float_as_uint(As[bf][mr + group    ][kk + tg + 4]);
        af[i][3] = __float_as_uint(As[bf][mr + group + 8][kk + tg + 4]);
      }
#pragma unroll
      for (int j = 0; j < 8; j++) {
        int nr = wn * 64 + j * 8;
        bfr[j][0] = __float_as_uint(Bs[bf][nr + group][kk + tg    ]);
        bfr[j][1] = __float_as_uint(Bs[bf][nr + group][kk + tg + 4]);
      }
#pragma unroll
      for (int i = 0; i < 2; i++)
#pragma unroll
        for (int j = 0; j < 8; j++)
          mma_tf32(acc[i][j], af[i], bfr[j]);
    }
    __syncthreads();
  }
#undef NT_LOAD
  if (epi == 0) {
#pragma unroll
    for (int i = 0; i < 2; i++) {
      int row0 = m0 + wm * 32 + i * 16 + group;
#pragma unroll
      for (int j = 0; j < 8; j++) {
        int col = n0 + wn * 64 + j * 8 + tg * 2;
        if (col < N) {
          *(float2*)&C[(size_t)row0 * N + col]       = make_float2(acc[i][j][0], acc[i][j][1]);
          *(float2*)&C[(size_t)(row0 + 8) * N + col] = make_float2(acc[i][j][2], acc[i][j][3]);
        }
      }
    }
  } else {
#pragma unroll
    for (int i = 0; i < 2; i++) {
      int row0 = m0 + wm * 32 + i * 16 + group;
      int ra = remap_row(row0), rb = remap_row(row0 + 8);
#pragma unroll
      for (int j = 0; j < 8; j++) {
        int col = n0 + wn * 64 + j * 8 + tg * 2;
        float b0 = bias[col], b1 = bias[col + 1];
        size_t oa = (size_t)ra * N + col, ob = (size_t)rb * N + col;
        float2 r0 = *(const float2*)&resid[oa];
        float2 r1 = *(const float2*)&resid[ob];
        *(float2*)&C[oa] = make_float2(geluf(acc[i][j][0] + b0) + r0.x,
                                       geluf(acc[i][j][1] + b1) + r0.y);
        *(float2*)&C[ob] = make_float2(geluf(acc[i][j][2] + b0) + r1.x,
                                       geluf(acc[i][j][3] + b1) + r1.y);
      }
    }
  }
}

// ================= GEMM TN (templated M-tile + split-K) =================
// C[M,N] = At^T @ B^T ; At is [K, lda] (m contiguous).
// blockIdx.z = batch*nsplit + split. Output written to C + z*sC (partials if nsplit>1).
template<int MT, int WMW>
__global__ __launch_bounds__(256) void gemm_tn(const float* __restrict__ At,
    const float* __restrict__ B, float* __restrict__ C, int M, int N, int K,
    int lda, int sA, int sC, int nsplit) {
  constexpr int WNW = 8 / WMW;          // warps along N
  constexpr int WNT = 128 / WNW;        // warp n-tile
  constexpr int JF  = WNT / 8;          // n fragments per warp
  constexpr int AST = MT + 8;           // A smem stride (== 8 mod 32: conflict-free)
  const int z = blockIdx.z;
  const int b = z / nsplit, s = z - b * nsplit;
  const int Kp = K / nsplit;
  At += (size_t)b * sA + (size_t)(s * Kp) * lda;
  C  += (size_t)z * sC;
  extern __shared__ float sm[];
  float (*Asr)[32][AST] = (float(*)[32][AST])sm;
  float (*Bs)[128][36]  = (float(*)[128][36])(sm + 2*32*AST);
  const int tid = threadIdx.x;
  const int wid = tid >> 5, lane = tid & 31;
  const int wm = wid % WMW, wn = wid / WMW;
  const int group = lane >> 2, tg = lane & 3;
  const int m0 = blockIdx.y * MT, n0 = blockIdx.x * 128;
  const int lr = tid >> 3, lk = tid & 7;
  const int akk = tid >> 3, amc = tid & 7;
  const int KC = Kp / 32;

  float acc[2][JF][4] = {};

#define TN_LOAD(c) do { \
    int k0 = (c) * 32; int bf_ = (c) & 1; \
    _Pragma("unroll") \
    for (int pass = 0; pass < MT/32; ++pass) { \
      int mc = amc + pass * 8; \
      cp16(&Asr[bf_][akk][mc*4], &At[(size_t)(k0 + akk)*lda + m0 + mc*4]); \
    } \
    _Pragma("unroll") \
    for (int pass = 0; pass < 4; ++pass) { \
      int r = lr + pass * 32; \
      cp16z(&Bs[bf_][r][lk*4], &B[(size_t)(n0 + r)*K + s*Kp + k0 + lk*4], n0 + r < N); \
    } \
    CP_COMMIT(); \
  } while (0)

  TN_LOAD(0);
  for (int c = 0; c < KC; ++c) {
    if (c + 1 < KC) { TN_LOAD(c + 1); CP_WAIT1(); }
    else            { CP_WAIT0(); }
    __syncthreads();
    const int bf = c & 1;
#pragma unroll
    for (int ks = 0; ks < 4; ++ks) {
      int kk = ks * 8;
      uint32_t af[2][4], bfr[JF][2];
#pragma unroll
      for (int i = 0; i < 2; i++) {
        int mr = wm * 32 + i * 16;
        af[i][0] = __float_as_uint(Asr[bf][kk + tg    ][mr + group    ]);
        af[i][1] = __float_as_uint(Asr[bf][kk + tg    ][mr + group + 8]);
        af[i][2] = __float_as_uint(Asr[bf][kk + tg + 4][mr + group    ]);
        af[i][3] = __float_as_uint(Asr[bf][kk + tg + 4][mr + group + 8]);
      }
#pragma unroll
      for (int j = 0; j < JF; j++) {
        int nr = wn * WNT + j * 8;
        bfr[j][0] = __float_as_uint(Bs[bf][nr + group][kk + tg    ]);
        bfr[j][1] = __float_as_uint(Bs[bf][nr + group][kk + tg + 4]);
      }
#pragma unroll
      for (int i = 0; i < 2; i++)
#pragma unroll
        for (int j = 0; j < JF; j++)
          mma_tf32(acc[i][j], af[i], bfr[j]);
    }
    __syncthreads();
  }
#undef TN_LOAD
#pragma unroll
  for (int i = 0; i < 2; i++) {
    int row0 = m0 + wm * 32 + i * 16 + group;
#pragma unroll
    for (int j = 0; j < JF; j++) {
      int col = n0 + wn * WNT + j * 8 + tg * 2;
      if (col < N) {
        *(float2*)&C[(size_t)row0 * N + col]       = make_float2(acc[i][j][0], acc[i][j][1]);
        *(float2*)&C[(size_t)(row0 + 8) * N + col] = make_float2(acc[i][j][2], acc[i][j][3]);
      }
    }
  }
}
#define TN_SMEM_128 ((2*32*136 + 2*128*36)*4)
#define TN_SMEM_64  ((2*32*72  + 2*128*36)*4)

// ================= split-K reduce for dbc =================
__global__ void reduce_dbc() {
  int i = blockIdx.x * 256 + threadIdx.x;     // float4 index
  const int per = BATCH*SEQ*DBC_W/4;
  if (i >= per) return;
  const float4* p = (const float4*)g_dbcp;
  float4 a = p[i];
  // partials for batch b at z = b*XSPLIT + s; i spans [b][row][col]
  int b = i / (SEQ*DBC_W/4);
  int off = i - b * (SEQ*DBC_W/4);
  float4 r = make_float4(0.f,0.f,0.f,0.f);
#pragma unroll
  for (int s = 0; s < XSPLIT; s++) {
    float4 v = p[(size_t)(b*XSPLIT + s) * (SEQ*DBC_W/4) + off];
    r.x += v.x; r.y += v.y; r.z += v.z; r.w += v.w;
  }
  (void)a;
  ((float4*)g_dbc)[i] = r;
}

// ================= delta via mma (128d x 64t tiles) =================
__global__ __launch_bounds__(256) void delta_mma(const float* __restrict__ W,
    const float* __restrict__ dbc, const float* __restrict__ bias,
    float* __restrict__ outp) {
  __shared__ float As[128][36];
  __shared__ float Bs[64][36];
  const int b = blockIdx.z;
  const int tid = threadIdx.x;
  const int wid = tid >> 5, lane = tid & 31;
  const int wm = wid & 3, wn = wid >> 2;      // wn in 0..1 (32 t each)
  const int group = lane >> 2, tg = lane & 3;
  const int m0 = blockIdx.y * 128, n0 = blockIdx.x * 64;

  const float* Bb = dbc + (size_t)b * SEQ * DBC_W;
#pragma unroll
  for (int pass = 0; pass < 4; ++pass) {
    int i = tid + pass * 256;
    int r = i >> 3, q = i & 7;
    *(float4*)&As[r][q * 4] = *(const float4*)&W[(size_t)(m0 + r) * DTRANK + q * 4];
  }
#pragma unroll
  for (int pass = 0; pass < 2; ++pass) {
    int i = tid + pass * 256;
    int r = i >> 3, q = i & 7;
    *(float4*)&Bs[r][q * 4] = *(const float4*)&Bb[(size_t)(n0 + r) * DBC_W + q * 4];
  }
  __syncthreads();

  float acc[2][4][4] = {};
#pragma unroll
  for (int ks = 0; ks < 4; ++ks) {
    int kk = ks * 8;
    uint32_t af[2][4], bfr[4][2];
#pragma unroll
    for (int i = 0; i < 2; i++) {
      int mr = wm * 32 + i * 16;
      af[i][0] = __float_as_uint(As[mr + group    ][kk + tg    ]);
      af[i][1] = __float_as_uint(As[mr + group + 8][kk + tg    ]);
      af[i][2] = __float_as_uint(As[mr + group    ][kk + tg + 4]);
      af[i][3] = __float_as_uint(As[mr + group + 8][kk + tg + 4]);
    }
#pragma unroll
    for (int j = 0; j < 4; j++) {
      int nr = wn * 32 + j * 8;
      bfr[j][0] = __float_as_uint(Bs[nr + group][kk + tg    ]);
      bfr[j][1] = __float_as_uint(Bs[nr + group][kk + tg + 4]);
    }
#pragma unroll
    for (int i = 0; i < 2; i++)
#pragma unroll
      for (int j = 0; j < 4; j++)
        mma_tf32(acc[i][j], af[i], bfr[j]);
  }
  float* ob = outp + (size_t)b * DINNER * SEQ;
#pragma unroll
  for (int i = 0; i < 2; i++) {
    int d0 = m0 + wm * 32 + i * 16 + group;
    float ba = bias[d0], bb2 = bias[d0 + 8];
#pragma unroll
    for (int j = 0; j < 4; j++) {
      int t = n0 + wn * 32 + j * 8 + tg * 2;
      *(float2*)&ob[(size_t)d0 * SEQ + t] =
        make_float2(softplusf(acc[i][j][0] + ba), softplusf(acc[i][j][1] + ba));
      *(float2*)&ob[(size_t)(d0 + 8) * SEQ + t] =
        make_float2(softplusf(acc[i][j][2] + bb2), softplusf(acc[i][j][3] + bb2));
    }
  }
}

// ================= conv + silu + z-silu, transposed to [b,d,t] =================
__global__ void convz_kernel(const float* __restrict__ conv_w, const float* __restrict__ conv_b) {
  __shared__ float sx[67][33];
  __shared__ float sz[64][33];
  int b = blockIdx.z, t0 = blockIdx.x * 64, d0 = blockIdx.y * 32;
  int tid = threadIdx.y * 64 + threadIdx.x;
  for (int i = tid; i < 67*32; i += 256) {
    int r = i >> 5, c = i & 31;
    int t = t0 - 3 + r;
    sx[r][c] = (t >= 0) ? g_xz[(size_t)(b*SEQ + t)*2*DINNER + d0 + c] : 0.f;
  }
  for (int i = tid; i < 64*32; i += 256) {
    int r = i >> 5, c = i & 31;
    sz[r][c] = g_xz[(size_t)(b*SEQ + t0 + r)*2*DINNER + DINNER + d0 + c];
  }
  __syncthreads();
  int tx = threadIdx.x;
#pragma unroll
  for (int i = 0; i < 8; i++) {
    int dl = threadIdx.y * 8 + i;
    int d = d0 + dl;
    float w0 = conv_w[d*4+0], w1 = conv_w[d*4+1], w2 = conv_w[d*4+2], w3 = conv_w[d*4+3];
    float acc = conv_b[d];
    acc += sx[tx+0][dl]*w0 + sx[tx+1][dl]*w1 + sx[tx+2][dl]*w2 + sx[tx+3][dl]*w3;
    size_t o = (size_t)(b*DINNER + d)*SEQ + t0 + tx;
    g_ut[o] = siluf(acc);
    g_zt[o] = siluf(sz[tx][dl]);
  }
}

// ================= selective scan =================
__global__ void scan_kernel(const float* __restrict__ Dw, const float* __restrict__ A_log) {
  int warp = threadIdx.x >> 5, lane = threadIdx.x & 31;
  int g = blockIdx.x * 8 + warp;
  int b = g >> 10, d = g & 1023;
  __shared__ float sBC[32][64];
  __shared__ float sP[8][32][34];
  float An = -__expf(A_log[d*DSTATE + lane]);
  float Dd = Dw[d];
  float h = 0.f;
  const float* ut  = g_ut     + (size_t)(b*DINNER + d)*SEQ;
  const float* dtp = g_deltat + (size_t)(b*DINNER + d)*SEQ;
  const float* ztp = g_zt     + (size_t)(b*DINNER + d)*SEQ;
  float*       ytp = g_yt     + (size_t)(b*DINNER + d)*SEQ;

  for (int t0 = 0; t0 < SEQ; t0 += 32) {
    __syncthreads();
    for (int i = threadIdx.x; i < 32*64; i += 256) {
      int s = i >> 6, c = i & 63;
      sBC[s][c] = g_dbc[(size_t)(b*SEQ + t0 + s)*DBC_W + DSTATE + c];
    }
    __syncthreads();
    float du = ut[t0 + lane];
    float dd = dtp[t0 + lane];
    float sz = ztp[t0 + lane];
#pragma unroll 8
    for (int s = 0; s < 32; s++) {
      float delta_t = __shfl_sync(0xffffffffu, dd, s);
      float u_t     = __shfl_sync(0xffffffffu, du, s);
      float dA = __expf(delta_t * An);
      h = fmaf(dA, h, delta_t * u_t * sBC[s][lane]);
      sP[warp][s][lane] = h * sBC[s][32 + lane];
    }
    __syncwarp();
    float y = du * Dd;
#pragma unroll
    for (int i = 0; i < 32; i++) {
      int c = (lane + i) & 31;
      y += sP[warp][lane][c];
    }
    ytp[t0 + lane] = y * sz;
  }
}

// ================= layernorm =================
__global__ void ln_kernel(const float* __restrict__ lnw, const float* __restrict__ lnb) {
  int row = blockIdx.x;
  const float* y = g_y2 + (size_t)row * DMODEL;
  float*       o = g_yn + (size_t)row * DMODEL;
  int tid = threadIdx.x;
  int lane = tid & 31, wid = tid >> 5;
  float v[4], s = 0.f, s2 = 0.f;
#pragma unroll
  for (int i = 0; i < 4; i++) {
    float x = y[tid + i*128];
    v[i] = x; s += x; s2 += x*x;
  }
#pragma unroll
  for (int off = 16; off >= 1; off >>= 1) {
    s  += __shfl_xor_sync(0xffffffffu, s, off);
    s2 += __shfl_xor_sync(0xffffffffu, s2, off);
  }
  __shared__ float sh[10];
  if (lane == 0) { sh[wid] = s; sh[4 + wid] = s2; }
  __syncthreads();
  if (tid == 0) {
    float ts = sh[0] + sh[1] + sh[2] + sh[3];
    float ts2 = sh[4] + sh[5] + sh[6] + sh[7];
    float mu = ts * (1.f/DMODEL);
    float var = ts2 * (1.f/DMODEL) - mu*mu;
    sh[8] = mu;
    sh[9] = rsqrtf(var + 1e-5f);
  }
  __syncthreads();
  float mu = sh[8], inv = sh[9];
#pragma unroll
  for (int i = 0; i < 4; i++) {
    int c = tid + i*128;
    o[c] = (v[i] - mu) * inv * lnw[c] + lnb[c];
  }
}

// ================= launch =================
extern "C" void kernel_launch(void* const* d_in, const int* in_sizes, int n_in,
                              void* d_out, int out_size) {
  const float* tokens     = (const float*)d_in[0];
  const float* in_proj_w  = (const float*)d_in[1];
  const float* conv_w     = (const float*)d_in[2];
  const float* conv_b     = (const float*)d_in[3];
  const float* x_proj_w   = (const float*)d_in[4];
  const float* dt_proj_w  = (const float*)d_in[5];
  const float* dt_proj_b  = (const float*)d_in[6];
  const float* A_log      = (const float*)d_in[7];
  const float* Dw         = (const float*)d_in[8];
  const float* out_proj_w = (const float*)d_in[9];
  const float* ln_w       = (const float*)d_in[10];
  const float* ln_b       = (const float*)d_in[11];
  const float* lin_w      = (const float*)d_in[12];
  const float* lin_b      = (const float*)d_in[13];
  float* out = (float*)d_out;

  float *p_xz, *p_ut, *p_dbcp, *p_dbc, *p_deltat, *p_yt, *p_y2, *p_yn;
  cudaGetSymbolAddress((void**)&p_xz,     g_xz);
  cudaGetSymbolAddress((void**)&p_ut,     g_ut);
  cudaGetSymbolAddress((void**)&p_dbcp,   g_dbcp);
  cudaGetSymbolAddress((void**)&p_dbc,    g_dbc);
  cudaGetSymbolAddress((void**)&p_deltat, g_deltat);
  cudaGetSymbolAddress((void**)&p_yt,     g_yt);
  cudaGetSymbolAddress((void**)&p_y2,     g_y2);
  cudaGetSymbolAddress((void**)&p_yn,     g_yn);

  cudaFuncSetAttribute(gemm_nt, cudaFuncAttributeMaxDynamicSharedMemorySize, NT_SMEM);
  cudaFuncSetAttribute(gemm_tn<128,4>, cudaFuncAttributeMaxDynamicSharedMemorySize, TN_SMEM_128);
  cudaFuncSetAttribute(gemm_tn<64,2>,  cudaFuncAttributeMaxDynamicSharedMemorySize, TN_SMEM_64);

  // 1. xz = perm(tokens) @ in_proj_w^T
  gemm_nt<<<dim3(2*DINNER/128, NROWS/128), 256, NT_SMEM>>>(tokens, in_proj_w, p_xz,
                                                           NROWS, 2*DINNER, DMODEL,
                                                           1, 0, nullptr, nullptr);
  // 2. conv+silu -> ut ; silu(z) -> zt
  convz_kernel<<<dim3(SEQ/64, DINNER/32, BATCH), dim3(64,4)>>>(conv_w, conv_b);
  // 3. dbc partials (split-K=4): per-b 1024 x 96 x 1024
  gemm_tn<128,4><<<dim3(1, SEQ/128, BATCH*XSPLIT), 256, TN_SMEM_128>>>(
      p_ut, x_proj_w, p_dbcp, SEQ, DBC_W, DINNER, SEQ, DINNER*SEQ, SEQ*DBC_W, XSPLIT);
  // 3b. reduce partials -> dbc
  reduce_dbc<<<(BATCH*SEQ*DBC_W/4 + 255)/256, 256>>>();
  // 4. delta = softplus(dt @ W^T + b) -> [b,d,t]
  delta_mma<<<dim3(SEQ/64, DINNER/128, BATCH), 256>>>(dt_proj_w, p_dbc, dt_proj_b, p_deltat);
  // 5. scan -> yt[b,d,t]
  scan_kernel<<<NROWS/8, 256>>>(Dw, A_log);
  // 6. y2 = y @ out_proj_w^T (64-row tiles for occupancy)
  gemm_tn<64,2><<<dim3(DMODEL/128, SEQ/64, BATCH), 256, TN_SMEM_64>>>(
      p_yt, out_proj_w, p_y2, SEQ, DMODEL, DINNER, SEQ, DINNER*SEQ, SEQ*DMODEL, 1);
  // 7. layernorm
  ln_kernel<<<NROWS, 128>>>(ln_w, ln_b);
  // 8. out = gelu(yn @ lin_w^T + lin_b) + residual (fused epi + scatter)
  gemm_nt<<<dim3(DMODEL/128, NROWS/128), 256, NT_SMEM>>>(p_yn, lin_w, out,
                                                         NROWS, DMODEL, DMODEL,
                                                         0, 1, lin_b, tokens);
}

// round 7
// speedup vs baseline: 2.4483x; 1.0061x over previous
#include <cuda_runtime.h>
#include <cstdint>
#include <math.h>

#define BATCH  4
#define SEQ    1024
#define DMODEL 512
#define DINNER 1024
#define DSTATE 32
#define DTRANK 32
#define DBC_W  96
#define NROWS  (BATCH*SEQ)   // 4096
#define XSPLIT 4             // split-K factor for x_proj

// ================= scratch =================
__device__ float g_xz    [BATCH*SEQ*2*DINNER];
__device__ float g_ut    [BATCH*DINNER*SEQ];
__device__ float g_zt    [BATCH*DINNER*SEQ];
__device__ float g_dbcp  [XSPLIT*BATCH*SEQ*DBC_W];
__device__ float g_dbc   [BATCH*SEQ*DBC_W];
__device__ float g_deltat[BATCH*DINNER*SEQ];
__device__ float g_yt    [BATCH*DINNER*SEQ];
__device__ float g_y2    [BATCH*SEQ*DMODEL];
__device__ float g_yn    [BATCH*SEQ*DMODEL];

__device__ __forceinline__ int perm_src(int p) {
  int r = p >> 5, c = p & 31;
  if (r & 1) c = 31 - c;
  return (r << 5) | c;
}
__device__ __forceinline__ int remap_row(int m) {
  return (m & ~(SEQ - 1)) + perm_src(m & (SEQ - 1));
}
__device__ __forceinline__ float softplusf(float x) {
  return fmaxf(x, 0.f) + __logf(1.f + __expf(-fabsf(x)));
}
__device__ __forceinline__ float siluf(float x) {
  return __fdividef(x, 1.f + __expf(-x));
}
__device__ __forceinline__ float fast_erff(float x) {
  float ax = fabsf(x);
  float t = __frcp_rn(fmaf(0.3275911f, ax, 1.f));
  float p = t * fmaf(t, fmaf(t, fmaf(t, fmaf(t, 1.061405429f, -1.453152027f),
                     1.421413741f), -0.284496736f), 0.254829592f);
  float r = 1.f - p * __expf(-ax * ax);
  return copysignf(r, x);
}
__device__ __forceinline__ float geluf(float x) {
  return 0.5f * x * (1.f + fast_erff(x * 0.70710678118654752f));
}
__device__ __forceinline__ uint32_t smem_u32(const void* p) {
  uint32_t a;
  asm("{ .reg .u64 t; cvta.to.shared.u64 t, %1; cvt.u32.u64 %0, t; }" : "=r"(a) : "l"(p));
  return a;
}
__device__ __forceinline__ void cp16(void* dst, const void* src) {
  asm volatile("cp.async.cg.shared.global [%0], [%1], 16;"
               :: "r"(smem_u32(dst)), "l"(src));
}
__device__ __forceinline__ void cp16z(void* dst, const void* src, bool valid) {
  int sz = valid ? 16 : 0;
  asm volatile("cp.async.cg.shared.global [%0], [%1], 16, %2;"
               :: "r"(smem_u32(dst)), "l"(src), "r"(sz));
}
#define CP_COMMIT() asm volatile("cp.async.commit_group;" ::: "memory")
#define CP_WAIT1()  asm volatile("cp.async.wait_group 1;" ::: "memory")
#define CP_WAIT0()  asm volatile("cp.async.wait_group 0;" ::: "memory")

__device__ __forceinline__ void mma_tf32(float* c, const uint32_t* a, const uint32_t* b) {
  asm volatile(
    "mma.sync.aligned.m16n8k8.row.col.f32.tf32.tf32.f32 "
    "{%0,%1,%2,%3}, {%4,%5,%6,%7}, {%8,%9}, {%0,%1,%2,%3};"
    : "+f"(c[0]), "+f"(c[1]), "+f"(c[2]), "+f"(c[3])
    : "r"(a[0]), "r"(a[1]), "r"(a[2]), "r"(a[3]), "r"(b[0]), "r"(b[1]));
}

// ================= GEMM NT: C[M,N] = A[M,K] @ B[N,K]^T (3-stage pipeline) =========
#define NT_STAGE (2*128*36)                // floats per stage (A tile + B tile)
#define NT_SMEM3 (3*NT_STAGE*4)            // 110592 B -> 2 CTAs/SM
__global__ __launch_bounds__(256, 2) void gemm_nt(const float* __restrict__ A,
    const float* __restrict__ B, float* __restrict__ C, int M, int N, int K,
    int gatherA, int epi, const float* __restrict__ bias,
    const float* __restrict__ resid) {
  extern __shared__ float sm[];
  const int tid = threadIdx.x;
  const int wid = tid >> 5, lane = tid & 31;
  const int wm = wid & 3, wn = wid >> 2;
  const int group = lane >> 2, tg = lane & 3;
  const int m0 = blockIdx.y * 128, n0 = blockIdx.x * 128;
  const int lr = tid >> 3, lk = tid & 7;
  const int KC = K / 32;

  float acc[2][8][4] = {};

  int arow[4];
#pragma unroll
  for (int pass = 0; pass < 4; ++pass) {
    int m = m0 + lr + pass * 32;
    arow[pass] = gatherA ? remap_row(m) : m;
  }

#define NT_LOAD(c) do { \
    int k0 = (c) * 32; \
    float* stA = sm + ((c) % 3) * NT_STAGE; \
    float* stB = stA + 128*36; \
    _Pragma("unroll") \
    for (int pass = 0; pass < 4; ++pass) { \
      int r = lr + pass * 32; \
      cp16(stA + r*36 + lk*4, &A[(size_t)arow[pass]*K + k0 + lk*4]); \
      cp16z(stB + r*36 + lk*4, &B[(size_t)(n0 + r)*K + k0 + lk*4], n0 + r < N); \
    } \
    CP_COMMIT(); \
  } while (0)

  NT_LOAD(0);
  if (KC > 1) NT_LOAD(1);
  for (int c = 0; c < KC; ++c) {
    if (c + 1 < KC) CP_WAIT1(); else CP_WAIT0();
    __syncthreads();
    if (c + 2 < KC) NT_LOAD(c + 2);
    float (*As)[36] = (float(*)[36])(sm + (c % 3) * NT_STAGE);
    float (*Bs)[36] = As + 128;
#pragma unroll
    for (int ks = 0; ks < 4; ++ks) {
      int kk = ks * 8;
      uint32_t af[2][4], bfr[8][2];
#pragma unroll
      for (int i = 0; i < 2; i++) {
        int mr = wm * 32 + i * 16;
        af[i][0] = __float_as_uint(As[mr + group    ][kk + tg    ]);
        af[i][1] = __float_as_uint(As[mr + group + 8][kk + tg    ]);
        af[i][2] = __float_as_uint(As[mr + group    ][kk + tg + 4]);
        af[i][3] = __float_as_uint(As[mr + group + 8][kk + tg + 4]);
      }
#pragma unroll
      for (int j = 0; j < 8; j++) {
        int nr = wn * 64 + j * 8;
        bfr[j][0] = __float_as_uint(Bs[nr + group][kk + tg    ]);
        bfr[j][1] = __float_as_uint(Bs[nr + group][kk + tg + 4]);
      }
#pragma unroll
      for (int i = 0; i < 2; i++)
#pragma unroll
        for (int j = 0; j < 8; j++)
          mma_tf32(acc[i][j], af[i], bfr[j]);
    }
  }
#undef NT_LOAD
  if (epi == 0) {
#pragma unroll
    for (int i = 0; i < 2; i++) {
      int row0 = m0 + wm * 32 + i * 16 + group;
#pragma unroll
      for (int j = 0; j < 8; j++) {
        int col = n0 + wn * 64 + j * 8 + tg * 2;
        if (col < N) {
          *(float2*)&C[(size_t)row0 * N + col]       = make_float2(acc[i][j][0], acc[i][j][1]);
          *(float2*)&C[(size_t)(row0 + 8) * N + col] = make_float2(acc[i][j][2], acc[i][j][3]);
        }
      }
    }
  } else {
#pragma unroll
    for (int i = 0; i < 2; i++) {
      int row0 = m0 + wm * 32 + i * 16 + group;
      int ra = remap_row(row0), rb = remap_row(row0 + 8);
#pragma unroll
      for (int j = 0; j < 8; j++) {
        int col = n0 + wn * 64 + j * 8 + tg * 2;
        float b0 = bias[col], b1 = bias[col + 1];
        size_t oa = (size_t)ra * N + col, ob = (size_t)rb * N + col;
        float2 r0 = *(const float2*)&resid[oa];
        float2 r1 = *(const float2*)&resid[ob];
        *(float2*)&C[oa] = make_float2(geluf(acc[i][j][0] + b0) + r0.x,
                                       geluf(acc[i][j][1] + b1) + r0.y);
        *(float2*)&C[ob] = make_float2(geluf(acc[i][j][2] + b0) + r1.x,
                                       geluf(acc[i][j][3] + b1) + r1.y);
      }
    }
  }
}

// ================= GEMM TN (templated M-tile + split-K, 3-stage) =================
template<int MT, int WMW>
__global__ __launch_bounds__(256, 2) void gemm_tn(const float* __restrict__ At,
    const float* __restrict__ B, float* __restrict__ C, int M, int N, int K,
    int lda, int sA, int sC, int nsplit) {
  constexpr int WNW = 8 / WMW;
  constexpr int WNT = 128 / WNW;
  constexpr int JF  = WNT / 8;
  constexpr int AST = MT + 8;
  constexpr int STG = 32*AST + 128*36;      // floats per stage
  const int z = blockIdx.z;
  const int b = z / nsplit, s = z - b * nsplit;
  const int Kp = K / nsplit;
  At += (size_t)b * sA + (size_t)(s * Kp) * lda;
  C  += (size_t)z * sC;
  extern __shared__ float sm[];
  const int tid = threadIdx.x;
  const int wid = tid >> 5, lane = tid & 31;
  const int wm = wid % WMW, wn = wid / WMW;
  const int group = lane >> 2, tg = lane & 3;
  const int m0 = blockIdx.y * MT, n0 = blockIdx.x * 128;
  const int lr = tid >> 3, lk = tid & 7;
  const int akk = tid >> 3, amc = tid & 7;
  const int KC = Kp / 32;

  float acc[2][JF][4] = {};

#define TN_LOAD(c) do { \
    int k0 = (c) * 32; \
    float* stA = sm + ((c) % 3) * STG; \
    float* stB = stA + 32*AST; \
    _Pragma("unroll") \
    for (int pass = 0; pass < MT/32; ++pass) { \
      int mc = amc + pass * 8; \
      cp16(stA + akk*AST + mc*4, &At[(size_t)(k0 + akk)*lda + m0 + mc*4]); \
    } \
    _Pragma("unroll") \
    for (int pass = 0; pass < 4; ++pass) { \
      int r = lr + pass * 32; \
      cp16z(stB + r*36 + lk*4, &B[(size_t)(n0 + r)*K + s*Kp + k0 + lk*4], n0 + r < N); \
    } \
    CP_COMMIT(); \
  } while (0)

  TN_LOAD(0);
  if (KC > 1) TN_LOAD(1);
  for (int c = 0; c < KC; ++c) {
    if (c + 1 < KC) CP_WAIT1(); else CP_WAIT0();
    __syncthreads();
    if (c + 2 < KC) TN_LOAD(c + 2);
    float (*Asr)[AST] = (float(*)[AST])(sm + (c % 3) * STG);
    float (*Bs)[36]   = (float(*)[36])(sm + (c % 3) * STG + 32*AST);
#pragma unroll
    for (int ks = 0; ks < 4; ++ks) {
      int kk = ks * 8;
      uint32_t af[2][4], bfr[JF][2];
#pragma unroll
      for (int i = 0; i < 2; i++) {
        int mr = wm * 32 + i * 16;
        af[i][0] = __float_as_uint(Asr[kk + tg    ][mr + group    ]);
        af[i][1] = __float_as_uint(Asr[kk + tg    ][mr + group + 8]);
        af[i][2] = __float_as_uint(Asr[kk + tg + 4][mr + group    ]);
        af[i][3] = __float_as_uint(Asr[kk + tg + 4][mr + group + 8]);
      }
#pragma unroll
      for (int j = 0; j < JF; j++) {
        int nr = wn * WNT + j * 8;
        bfr[j][0] = __float_as_uint(Bs[nr + group][kk + tg    ]);
        bfr[j][1] = __float_as_uint(Bs[nr + group][kk + tg + 4]);
      }
#pragma unroll
      for (int i = 0; i < 2; i++)
#pragma unroll
        for (int j = 0; j < JF; j++)
          mma_tf32(acc[i][j], af[i], bfr[j]);
    }
  }
#undef TN_LOAD
#pragma unroll
  for (int i = 0; i < 2; i++) {
    int row0 = m0 + wm * 32 + i * 16 + group;
#pragma unroll
    for (int j = 0; j < JF; j++) {
      int col = n0 + wn * WNT + j * 8 + tg * 2;
      if (col < N) {
        *(float2*)&C[(size_t)row0 * N + col]       = make_float2(acc[i][j][0], acc[i][j][1]);
        *(float2*)&C[(size_t)(row0 + 8) * N + col] = make_float2(acc[i][j][2], acc[i][j][3]);
      }
    }
  }
}
#define TN_SMEM3_128 (3*(32*136 + 128*36)*4)
#define TN_SMEM3_64  (3*(32*72  + 128*36)*4)

// ================= split-K reduce for dbc =================
__global__ void reduce_dbc() {
  int i = blockIdx.x * 256 + threadIdx.x;
  const int per = BATCH*SEQ*DBC_W/4;
  if (i >= per) return;
  const float4* p = (const float4*)g_dbcp;
  int b = i / (SEQ*DBC_W/4);
  int off = i - b * (SEQ*DBC_W/4);
  float4 r = make_float4(0.f,0.f,0.f,0.f);
#pragma unroll
  for (int s = 0; s < XSPLIT; s++) {
    float4 v = p[(size_t)(b*XSPLIT + s) * (SEQ*DBC_W/4) + off];
    r.x += v.x; r.y += v.y; r.z += v.z; r.w += v.w;
  }
  ((float4*)g_dbc)[i] = r;
}

// ================= delta via mma (128d x 64t tiles) =================
__global__ __launch_bounds__(256) void delta_mma(const float* __restrict__ W,
    const float* __restrict__ dbc, const float* __restrict__ bias,
    float* __restrict__ outp) {
  __shared__ float As[128][36];
  __shared__ float Bs[64][36];
  const int b = blockIdx.z;
  const int tid = threadIdx.x;
  const int wid = tid >> 5, lane = tid & 31;
  const int wm = wid & 3, wn = wid >> 2;
  const int group = lane >> 2, tg = lane & 3;
  const int m0 = blockIdx.y * 128, n0 = blockIdx.x * 64;

  const float* Bb = dbc + (size_t)b * SEQ * DBC_W;
#pragma unroll
  for (int pass = 0; pass < 4; ++pass) {
    int i = tid + pass * 256;
    int r = i >> 3, q = i & 7;
    *(float4*)&As[r][q * 4] = *(const float4*)&W[(size_t)(m0 + r) * DTRANK + q * 4];
  }
#pragma unroll
  for (int pass = 0; pass < 2; ++pass) {
    int i = tid + pass * 256;
    int r = i >> 3, q = i & 7;
    *(float4*)&Bs[r][q * 4] = *(const float4*)&Bb[(size_t)(n0 + r) * DBC_W + q * 4];
  }
  __syncthreads();

  float acc[2][4][4] = {};
#pragma unroll
  for (int ks = 0; ks < 4; ++ks) {
    int kk = ks * 8;
    uint32_t af[2][4], bfr[4][2];
#pragma unroll
    for (int i = 0; i < 2; i++) {
      int mr = wm * 32 + i * 16;
      af[i][0] = __float_as_uint(As[mr + group    ][kk + tg    ]);
      af[i][1] = __float_as_uint(As[mr + group + 8][kk + tg    ]);
      af[i][2] = __float_as_uint(As[mr + group    ][kk + tg + 4]);
      af[i][3] = __float_as_uint(As[mr + group + 8][kk + tg + 4]);
    }
#pragma unroll
    for (int j = 0; j < 4; j++) {
      int nr = wn * 32 + j * 8;
      bfr[j][0] = __float_as_uint(Bs[nr + group][kk + tg    ]);
      bfr[j][1] = __float_as_uint(Bs[nr + group][kk + tg + 4]);
    }
#pragma unroll
    for (int i = 0; i < 2; i++)
#pragma unroll
      for (int j = 0; j < 4; j++)
        mma_tf32(acc[i][j], af[i], bfr[j]);
  }
  float* ob = outp + (size_t)b * DINNER * SEQ;
#pragma unroll
  for (int i = 0; i < 2; i++) {
    int d0 = m0 + wm * 32 + i * 16 + group;
    float ba = bias[d0], bb2 = bias[d0 + 8];
#pragma unroll
    for (int j = 0; j < 4; j++) {
      int t = n0 + wn * 32 + j * 8 + tg * 2;
      *(float2*)&ob[(size_t)d0 * SEQ + t] =
        make_float2(softplusf(acc[i][j][0] + ba), softplusf(acc[i][j][1] + ba));
      *(float2*)&ob[(size_t)(d0 + 8) * SEQ + t] =
        make_float2(softplusf(acc[i][j][2] + bb2), softplusf(acc[i][j][3] + bb2));
    }
  }
}

// ================= conv + silu + z-silu, transposed to [b,d,t] =================
__global__ void convz_kernel(const float* __restrict__ conv_w, const float* __restrict__ conv_b) {
  __shared__ float sx[67][33];
  __shared__ float sz[64][33];
  int b = blockIdx.z, t0 = blockIdx.x * 64, d0 = blockIdx.y * 32;
  int tid = threadIdx.y * 64 + threadIdx.x;
  for (int i = tid; i < 67*32; i += 256) {
    int r = i >> 5, c = i & 31;
    int t = t0 - 3 + r;
    sx[r][c] = (t >= 0) ? g_xz[(size_t)(b*SEQ + t)*2*DINNER + d0 + c] : 0.f;
  }
  for (int i = tid; i < 64*32; i += 256) {
    int r = i >> 5, c = i & 31;
    sz[r][c] = g_xz[(size_t)(b*SEQ + t0 + r)*2*DINNER + DINNER + d0 + c];
  }
  __syncthreads();
  int tx = threadIdx.x;
#pragma unroll
  for (int i = 0; i < 8; i++) {
    int dl = threadIdx.y * 8 + i;
    int d = d0 + dl;
    float w0 = conv_w[d*4+0], w1 = conv_w[d*4+1], w2 = conv_w[d*4+2], w3 = conv_w[d*4+3];
    float acc = conv_b[d];
    acc += sx[tx+0][dl]*w0 + sx[tx+1][dl]*w1 + sx[tx+2][dl]*w2 + sx[tx+3][dl]*w3;
    size_t o = (size_t)(b*DINNER + d)*SEQ + t0 + tx;
    g_ut[o] = siluf(acc);
    g_zt[o] = siluf(sz[tx][dl]);
  }
}

// ================= selective scan =================
__global__ void scan_kernel(const float* __restrict__ Dw, const float* __restrict__ A_log) {
  int warp = threadIdx.x >> 5, lane = threadIdx.x & 31;
  int g = blockIdx.x * 8 + warp;
  int b = g >> 10, d = g & 1023;
  __shared__ float sBC[32][64];
  __shared__ float sP[8][32][34];
  float An = -__expf(A_log[d*DSTATE + lane]);
  float Dd = Dw[d];
  float h = 0.f;
  const float* ut  = g_ut     + (size_t)(b*DINNER + d)*SEQ;
  const float* dtp = g_deltat + (size_t)(b*DINNER + d)*SEQ;
  const float* ztp = g_zt     + (size_t)(b*DINNER + d)*SEQ;
  float*       ytp = g_yt     + (size_t)(b*DINNER + d)*SEQ;

  for (int t0 = 0; t0 < SEQ; t0 += 32) {
    __syncthreads();
    for (int i = threadIdx.x; i < 32*64; i += 256) {
      int s = i >> 6, c = i & 63;
      sBC[s][c] = g_dbc[(size_t)(b*SEQ + t0 + s)*DBC_W + DSTATE + c];
    }
    __syncthreads();
    float du = ut[t0 + lane];
    float dd = dtp[t0 + lane];
    float sz = ztp[t0 + lane];
#pragma unroll 8
    for (int s = 0; s < 32; s++) {
      float delta_t = __shfl_sync(0xffffffffu, dd, s);
      float u_t     = __shfl_sync(0xffffffffu, du, s);
      float dA = __expf(delta_t * An);
      h = fmaf(dA, h, delta_t * u_t * sBC[s][lane]);
      sP[warp][s][lane] = h * sBC[s][32 + lane];
    }
    __syncwarp();
    float y = du * Dd;
#pragma unroll
    for (int i = 0; i < 32; i++) {
      int c = (lane + i) & 31;
      y += sP[warp][lane][c];
    }
    ytp[t0 + lane] = y * sz;
  }
}

// ================= layernorm =================
__global__ void ln_kernel(const float* __restrict__ lnw, const float* __restrict__ lnb) {
  int row = blockIdx.x;
  const float* y = g_y2 + (size_t)row * DMODEL;
  float*       o = g_yn + (size_t)row * DMODEL;
  int tid = threadIdx.x;
  int lane = tid & 31, wid = tid >> 5;
  float v[4], s = 0.f, s2 = 0.f;
#pragma unroll
  for (int i = 0; i < 4; i++) {
    float x = y[tid + i*128];
    v[i] = x; s += x; s2 += x*x;
  }
#pragma unroll
  for (int off = 16; off >= 1; off >>= 1) {
    s  += __shfl_xor_sync(0xffffffffu, s, off);
    s2 += __shfl_xor_sync(0xffffffffu, s2, off);
  }
  __shared__ float sh[10];
  if (lane == 0) { sh[wid] = s; sh[4 + wid] = s2; }
  __syncthreads();
  if (tid == 0) {
    float ts = sh[0] + sh[1] + sh[2] + sh[3];
    float ts2 = sh[4] + sh[5] + sh[6] + sh[7];
    float mu = ts * (1.f/DMODEL);
    float var = ts2 * (1.f/DMODEL) - mu*mu;
    sh[8] = mu;
    sh[9] = rsqrtf(var + 1e-5f);
  }
  __syncthreads();
  float mu = sh[8], inv = sh[9];
#pragma unroll
  for (int i = 0; i < 4; i++) {
    int c = tid + i*128;
    o[c] = (v[i] - mu) * inv * lnw[c] + lnb[c];
  }
}

// ================= launch =================
extern "C" void kernel_launch(void* const* d_in, const int* in_sizes, int n_in,
                              void* d_out, int out_size) {
  const float* tokens     = (const float*)d_in[0];
  const float* in_proj_w  = (const float*)d_in[1];
  const float* conv_w     = (const float*)d_in[2];
  const float* conv_b     = (const float*)d_in[3];
  const float* x_proj_w   = (const float*)d_in[4];
  const float* dt_proj_w  = (const float*)d_in[5];
  const float* dt_proj_b  = (const float*)d_in[6];
  const float* A_log      = (const float*)d_in[7];
  const float* Dw         = (const float*)d_in[8];
  const float* out_proj_w = (const float*)d_in[9];
  const float* ln_w       = (const float*)d_in[10];
  const float* ln_b       = (const float*)d_in[11];
  const float* lin_w      = (const float*)d_in[12];
  const float* lin_b      = (const float*)d_in[13];
  float* out = (float*)d_out;

  float *p_xz, *p_ut, *p_dbcp, *p_dbc, *p_deltat, *p_yt, *p_y2, *p_yn;
  cudaGetSymbolAddress((void**)&p_xz,     g_xz);
  cudaGetSymbolAddress((void**)&p_ut,     g_ut);
  cudaGetSymbolAddress((void**)&p_dbcp,   g_dbcp);
  cudaGetSymbolAddress((void**)&p_dbc,    g_dbc);
  cudaGetSymbolAddress((void**)&p_deltat, g_deltat);
  cudaGetSymbolAddress((void**)&p_yt,     g_yt);
  cudaGetSymbolAddress((void**)&p_y2,     g_y2);
  cudaGetSymbolAddress((void**)&p_yn,     g_yn);

  cudaFuncSetAttribute(gemm_nt, cudaFuncAttributeMaxDynamicSharedMemorySize, NT_SMEM3);
  cudaFuncSetAttribute(gemm_tn<128,4>, cudaFuncAttributeMaxDynamicSharedMemorySize, TN_SMEM3_128);
  cudaFuncSetAttribute(gemm_tn<64,2>,  cudaFuncAttributeMaxDynamicSharedMemorySize, TN_SMEM3_64);

  // 1. xz = perm(tokens) @ in_proj_w^T
  gemm_nt<<<dim3(2*DINNER/128, NROWS/128), 256, NT_SMEM3>>>(tokens, in_proj_w, p_xz,
                                                            NROWS, 2*DINNER, DMODEL,
                                                            1, 0, nullptr, nullptr);
  // 2. conv+silu -> ut ; silu(z) -> zt
  convz_kernel<<<dim3(SEQ/64, DINNER/32, BATCH), dim3(64,4)>>>(conv_w, conv_b);
  // 3. dbc partials (split-K=4)
  gemm_tn<128,4><<<dim3(1, SEQ/128, BATCH*XSPLIT), 256, TN_SMEM3_128>>>(
      p_ut, x_proj_w, p_dbcp, SEQ, DBC_W, DINNER, SEQ, DINNER*SEQ, SEQ*DBC_W, XSPLIT);
  // 3b. reduce partials
  reduce_dbc<<<(BATCH*SEQ*DBC_W/4 + 255)/256, 256>>>();
  // 4. delta
  delta_mma<<<dim3(SEQ/64, DINNER/128, BATCH), 256>>>(dt_proj_w, p_dbc, dt_proj_b, p_deltat);
  // 5. scan
  scan_kernel<<<NROWS/8, 256>>>(Dw, A_log);
  // 6. y2 = y @ out_proj_w^T
  gemm_tn<64,2><<<dim3(DMODEL/128, SEQ/64, BATCH), 256, TN_SMEM3_64>>>(
      p_yt, out_proj_w, p_y2, SEQ, DMODEL, DINNER, SEQ, DINNER*SEQ, SEQ*DMODEL, 1);
  // 7. layernorm
  ln_kernel<<<NROWS, 128>>>(ln_w, ln_b);
  // 8. out = gelu(yn @ lin_w^T + lin_b) + residual
  gemm_nt<<<dim3(DMODEL/128, NROWS/128), 256, NT_SMEM3>>>(p_yn, lin_w, out,
                                                          NROWS, DMODEL, DMODEL,
                                                          0, 1, lin_b, tokens);
}

// round 8
// speedup vs baseline: 2.6247x; 1.0721x over previous
#include <cuda_runtime.h>
#include <cstdint>
#include <math.h>

#define BATCH  4
#define SEQ    1024
#define DMODEL 512
#define DINNER 1024
#define DSTATE 32
#define DTRANK 32
#define DBC_W  96
#define NROWS  (BATCH*SEQ)   // 4096
#define XSPLIT 4

// ================= scratch =================
__device__ float g_xz    [BATCH*SEQ*2*DINNER];
__device__ float g_ut    [BATCH*DINNER*SEQ];
__device__ float g_zt    [BATCH*DINNER*SEQ];
__device__ float g_dbcp  [XSPLIT*BATCH*SEQ*DBC_W];
__device__ float g_dbc   [BATCH*SEQ*DBC_W];
__device__ float g_deltat[BATCH*DINNER*SEQ];
__device__ float g_yt    [BATCH*DINNER*SEQ];
__device__ float g_y2    [BATCH*SEQ*DMODEL];
__device__ float g_yn    [BATCH*SEQ*DMODEL];

__device__ __forceinline__ int perm_src(int p) {
  int r = p >> 5, c = p & 31;
  if (r & 1) c = 31 - c;
  return (r << 5) | c;
}
__device__ __forceinline__ int remap_row(int m) {
  return (m & ~(SEQ - 1)) + perm_src(m & (SEQ - 1));
}
__device__ __forceinline__ float softplusf(float x) {
  return fmaxf(x, 0.f) + __logf(1.f + __expf(-fabsf(x)));
}
__device__ __forceinline__ float siluf(float x) {
  return __fdividef(x, 1.f + __expf(-x));
}
__device__ __forceinline__ float fast_erff(float x) {
  float ax = fabsf(x);
  float t = __frcp_rn(fmaf(0.3275911f, ax, 1.f));
  float p = t * fmaf(t, fmaf(t, fmaf(t, fmaf(t, 1.061405429f, -1.453152027f),
                     1.421413741f), -0.284496736f), 0.254829592f);
  float r = 1.f - p * __expf(-ax * ax);
  return copysignf(r, x);
}
__device__ __forceinline__ float geluf(float x) {
  return 0.5f * x * (1.f + fast_erff(x * 0.70710678118654752f));
}
__device__ __forceinline__ uint32_t smem_u32(const void* p) {
  uint32_t a;
  asm("{ .reg .u64 t; cvta.to.shared.u64 t, %1; cvt.u32.u64 %0, t; }" : "=r"(a) : "l"(p));
  return a;
}
__device__ __forceinline__ void cp16(void* dst, const void* src) {
  asm volatile("cp.async.cg.shared.global [%0], [%1], 16;"
               :: "r"(smem_u32(dst)), "l"(src));
}
__device__ __forceinline__ void cp16z(void* dst, const void* src, bool valid) {
  int sz = valid ? 16 : 0;
  asm volatile("cp.async.cg.shared.global [%0], [%1], 16, %2;"
               :: "r"(smem_u32(dst)), "l"(src), "r"(sz));
}
#define CP_COMMIT() asm volatile("cp.async.commit_group;" ::: "memory")
#define CP_WAIT1()  asm volatile("cp.async.wait_group 1;" ::: "memory")
#define CP_WAIT0()  asm volatile("cp.async.wait_group 0;" ::: "memory")

#define LDSM4(r0, r1, r2, r3, addr) \
  asm volatile("ldmatrix.sync.aligned.m8n8.x4.shared.b16 {%0,%1,%2,%3}, [%4];" \
    : "=r"(r0), "=r"(r1), "=r"(r2), "=r"(r3) : "r"(addr))

__device__ __forceinline__ void mma_tf32(float* c, const uint32_t* a, const uint32_t* b) {
  asm volatile(
    "mma.sync.aligned.m16n8k8.row.col.f32.tf32.tf32.f32 "
    "{%0,%1,%2,%3}, {%4,%5,%6,%7}, {%8,%9}, {%0,%1,%2,%3};"
    : "+f"(c[0]), "+f"(c[1]), "+f"(c[2]), "+f"(c[3])
    : "r"(a[0]), "r"(a[1]), "r"(a[2]), "r"(a[3]), "r"(b[0]), "r"(b[1]));
}

// ================= GEMM NT (swizzled smem + ldmatrix), 3-stage ==================
// C[M,N] = A[M,K] @ B[N,K]^T. N % 128 == 0 (no guards).
// Smem tile: 128 rows x 32 floats; element (r,c) at r*32 + (c ^ ((r&7)<<2)).
#define NT_STAGE (2*128*32)
#define NT_SMEM3 (3*NT_STAGE*4)          // 98304 B
__global__ __launch_bounds__(256, 2) void gemm_nt(const float* __restrict__ A,
    const float* __restrict__ B, float* __restrict__ C, int M, int N, int K,
    int gatherA, int epi, const float* __restrict__ bias,
    const float* __restrict__ resid) {
  extern __shared__ float sm[];
  const uint32_t sbase = smem_u32(sm);
  const int tid = threadIdx.x;
  const int wid = tid >> 5, lane = tid & 31;
  const int wm = wid & 3, wn = wid >> 2;
  const int group = lane >> 2, tg = lane & 3;
  const int m0 = blockIdx.y * 128, n0 = blockIdx.x * 128;
  const int lr = tid >> 3, lk = tid & 7;
  const int KC = K / 32;

  // ldmatrix lane geometry
  int a_row[2], b_row[4];
#pragma unroll
  for (int i = 0; i < 2; i++)
    a_row[i] = wm * 32 + i * 16 + (lane & 7) + ((lane & 8) ? 8 : 0);
#pragma unroll
  for (int j2 = 0; j2 < 4; j2++)
    b_row[j2] = wn * 64 + j2 * 16 + (lane & 7) + ((lane & 16) ? 8 : 0);
  const int a_qc = (lane & 16) ? 1 : 0;
  const int b_qc = (lane & 8) ? 1 : 0;

  float acc[2][8][4] = {};

  int arow[4];
#pragma unroll
  for (int pass = 0; pass < 4; ++pass) {
    int m = m0 + lr + pass * 32;
    arow[pass] = gatherA ? remap_row(m) : m;
  }

#define NT_LOAD(c) do { \
    int k0 = (c) * 32; \
    float* st = sm + ((c) % 3) * NT_STAGE; \
    _Pragma("unroll") \
    for (int pass = 0; pass < 4; ++pass) { \
      int r = lr + pass * 32; \
      int sc = (lk ^ (r & 7)) * 4; \
      cp16(st + r * 32 + sc, &A[(size_t)arow[pass] * K + k0 + lk * 4]); \
      cp16(st + 128 * 32 + r * 32 + sc, &B[(size_t)(n0 + r) * K + k0 + lk * 4]); \
    } \
    CP_COMMIT(); \
  } while (0)

  NT_LOAD(0);
  if (KC > 1) NT_LOAD(1);
  for (int c = 0; c < KC; ++c) {
    if (c + 1 < KC) CP_WAIT1(); else CP_WAIT0();
    __syncthreads();
    if (c + 2 < KC) NT_LOAD(c + 2);
    const uint32_t stA = sbase + ((c % 3) * NT_STAGE) * 4;
    const uint32_t stB = stA + 128 * 32 * 4;
#pragma unroll
    for (int ks = 0; ks < 4; ++ks) {
      uint32_t af[2][4], bfr[8][2];
#pragma unroll
      for (int i = 0; i < 2; i++) {
        uint32_t ad = stA + a_row[i] * 128 + ((((2 * ks + a_qc) ^ (a_row[i] & 7))) << 4);
        LDSM4(af[i][0], af[i][1], af[i][2], af[i][3], ad);
      }
#pragma unroll
      for (int j2 = 0; j2 < 4; j2++) {
        uint32_t bd = stB + b_row[j2] * 128 + ((((2 * ks + b_qc) ^ (b_row[j2] & 7))) << 4);
        uint32_t r0, r1, r2, r3;
        LDSM4(r0, r1, r2, r3, bd);
        bfr[2*j2][0] = r0; bfr[2*j2][1] = r1;
        bfr[2*j2+1][0] = r2; bfr[2*j2+1][1] = r3;
      }
#pragma unroll
      for (int i = 0; i < 2; i++)
#pragma unroll
        for (int j = 0; j < 8; j++)
          mma_tf32(acc[i][j], af[i], bfr[j]);
    }
  }
#undef NT_LOAD
  if (epi == 0) {
#pragma unroll
    for (int i = 0; i < 2; i++) {
      int row0 = m0 + wm * 32 + i * 16 + group;
#pragma unroll
      for (int j = 0; j < 8; j++) {
        int col = n0 + wn * 64 + j * 8 + tg * 2;
        *(float2*)&C[(size_t)row0 * N + col]       = make_float2(acc[i][j][0], acc[i][j][1]);
        *(float2*)&C[(size_t)(row0 + 8) * N + col] = make_float2(acc[i][j][2], acc[i][j][3]);
      }
    }
  } else {
#pragma unroll
    for (int i = 0; i < 2; i++) {
      int row0 = m0 + wm * 32 + i * 16 + group;
      int ra = remap_row(row0), rb = remap_row(row0 + 8);
#pragma unroll
      for (int j = 0; j < 8; j++) {
        int col = n0 + wn * 64 + j * 8 + tg * 2;
        float b0 = bias[col], b1 = bias[col + 1];
        size_t oa = (size_t)ra * N + col, ob = (size_t)rb * N + col;
        float2 r0 = *(const float2*)&resid[oa];
        float2 r1 = *(const float2*)&resid[ob];
        *(float2*)&C[oa] = make_float2(geluf(acc[i][j][0] + b0) + r0.x,
                                       geluf(acc[i][j][1] + b1) + r0.y);
        *(float2*)&C[ob] = make_float2(geluf(acc[i][j][2] + b0) + r1.x,
                                       geluf(acc[i][j][3] + b1) + r1.y);
      }
    }
  }
}

// ================= GEMM TN (A scalar-LDS k-major, B ldmatrix), 3-stage ===========
template<int MT, int WMW>
__global__ __launch_bounds__(256, 2) void gemm_tn(const float* __restrict__ At,
    const float* __restrict__ B, float* __restrict__ C, int M, int N, int K,
    int lda, int sA, int sC, int nsplit) {
  constexpr int WNW = 8 / WMW;
  constexpr int WNT = 128 / WNW;
  constexpr int JF  = WNT / 8;
  constexpr int JF2 = JF / 2;
  constexpr int AST = MT + 8;                    // k-major A stride (==8 mod 32)
  constexpr int STG = 32 * AST + 128 * 32;       // floats per stage
  const int z = blockIdx.z;
  const int b = z / nsplit, s = z - b * nsplit;
  const int Kp = K / nsplit;
  At += (size_t)b * sA + (size_t)(s * Kp) * lda;
  C  += (size_t)z * sC;
  extern __shared__ float sm[];
  const uint32_t sbase = smem_u32(sm);
  const int tid = threadIdx.x;
  const int wid = tid >> 5, lane = tid & 31;
  const int wm = wid % WMW, wn = wid / WMW;
  const int group = lane >> 2, tg = lane & 3;
  const int m0 = blockIdx.y * MT, n0 = blockIdx.x * 128;
  const int lr = tid >> 3, lk = tid & 7;
  const int akk = tid >> 3, amc = tid & 7;
  const int KC = Kp / 32;

  int b_row[JF2];
#pragma unroll
  for (int j2 = 0; j2 < JF2; j2++)
    b_row[j2] = wn * WNT + j2 * 16 + (lane & 7) + ((lane & 16) ? 8 : 0);
  const int b_qc = (lane & 8) ? 1 : 0;

  float acc[2][JF][4] = {};

#define TN_LOAD(c) do { \
    int k0 = (c) * 32; \
    float* stA_ = sm + ((c) % 3) * STG; \
    float* stB_ = stA_ + 32 * AST; \
    _Pragma("unroll") \
    for (int pass = 0; pass < MT/32; ++pass) { \
      int mc = amc + pass * 8; \
      cp16(stA_ + akk * AST + mc * 4, &At[(size_t)(k0 + akk) * lda + m0 + mc * 4]); \
    } \
    _Pragma("unroll") \
    for (int pass = 0; pass < 4; ++pass) { \
      int r = lr + pass * 32; \
      int sc = (lk ^ (r & 7)) * 4; \
      cp16z(stB_ + r * 32 + sc, &B[(size_t)(n0 + r) * K + s * Kp + k0 + lk * 4], n0 + r < N); \
    } \
    CP_COMMIT(); \
  } while (0)

  TN_LOAD(0);
  if (KC > 1) TN_LOAD(1);
  for (int c = 0; c < KC; ++c) {
    if (c + 1 < KC) CP_WAIT1(); else CP_WAIT0();
    __syncthreads();
    if (c + 2 < KC) TN_LOAD(c + 2);
    float (*Asr)[AST] = (float(*)[AST])(sm + (c % 3) * STG);
    const uint32_t stB = sbase + ((c % 3) * STG + 32 * AST) * 4;
#pragma unroll
    for (int ks = 0; ks < 4; ++ks) {
      int kk = ks * 8;
      uint32_t af[2][4], bfr[JF][2];
#pragma unroll
      for (int i = 0; i < 2; i++) {
        int mr = wm * 32 + i * 16;
        af[i][0] = __float_as_uint(Asr[kk + tg    ][mr + group    ]);
        af[i][1] = __float_as_uint(Asr[kk + tg    ][mr + group + 8]);
        af[i][2] = __float_as_uint(Asr[kk + tg + 4][mr + group    ]);
        af[i][3] = __float_as_uint(Asr[kk + tg + 4][mr + group + 8]);
      }
#pragma unroll
      for (int j2 = 0; j2 < JF2; j2++) {
        uint32_t bd = stB + b_row[j2] * 128 + ((((2 * ks + b_qc) ^ (b_row[j2] & 7))) << 4);
        uint32_t r0, r1, r2, r3;
        LDSM4(r0, r1, r2, r3, bd);
        bfr[2*j2][0] = r0; bfr[2*j2][1] = r1;
        bfr[2*j2+1][0] = r2; bfr[2*j2+1][1] = r3;
      }
#pragma unroll
      for (int i = 0; i < 2; i++)
#pragma unroll
        for (int j = 0; j < JF; j++)
          mma_tf32(acc[i][j], af[i], bfr[j]);
    }
  }
#undef TN_LOAD
#pragma unroll
  for (int i = 0; i < 2; i++) {
    int row0 = m0 + wm * 32 + i * 16 + group;
#pragma unroll
    for (int j = 0; j < JF; j++) {
      int col = n0 + wn * WNT + j * 8 + tg * 2;
      if (col < N) {
        *(float2*)&C[(size_t)row0 * N + col]       = make_float2(acc[i][j][0], acc[i][j][1]);
        *(float2*)&C[(size_t)(row0 + 8) * N + col] = make_float2(acc[i][j][2], acc[i][j][3]);
      }
    }
  }
}
#define TN_SMEM3_128 (3*(32*136 + 128*32)*4)
#define TN_SMEM3_64  (3*(32*72  + 128*32)*4)

// ================= split-K reduce for dbc =================
__global__ void reduce_dbc() {
  int i = blockIdx.x * 256 + threadIdx.x;
  const int per = BATCH*SEQ*DBC_W/4;
  if (i >= per) return;
  const float4* p = (const float4*)g_dbcp;
  int b = i / (SEQ*DBC_W/4);
  int off = i - b * (SEQ*DBC_W/4);
  float4 r = make_float4(0.f,0.f,0.f,0.f);
#pragma unroll
  for (int s = 0; s < XSPLIT; s++) {
    float4 v = p[(size_t)(b*XSPLIT + s) * (SEQ*DBC_W/4) + off];
    r.x += v.x; r.y += v.y; r.z += v.z; r.w += v.w;
  }
  ((float4*)g_dbc)[i] = r;
}

// ================= delta via mma (128d x 64t tiles) =================
__global__ __launch_bounds__(256) void delta_mma(const float* __restrict__ W,
    const float* __restrict__ dbc, const float* __restrict__ bias,
    float* __restrict__ outp) {
  __shared__ float As[128][36];
  __shared__ float Bs[64][36];
  const int b = blockIdx.z;
  const int tid = threadIdx.x;
  const int wid = tid >> 5, lane = tid & 31;
  const int wm = wid & 3, wn = wid >> 2;
  const int group = lane >> 2, tg = lane & 3;
  const int m0 = blockIdx.y * 128, n0 = blockIdx.x * 64;

  const float* Bb = dbc + (size_t)b * SEQ * DBC_W;
#pragma unroll
  for (int pass = 0; pass < 4; ++pass) {
    int i = tid + pass * 256;
    int r = i >> 3, q = i & 7;
    *(float4*)&As[r][q * 4] = *(const float4*)&W[(size_t)(m0 + r) * DTRANK + q * 4];
  }
#pragma unroll
  for (int pass = 0; pass < 2; ++pass) {
    int i = tid + pass * 256;
    int r = i >> 3, q = i & 7;
    *(float4*)&Bs[r][q * 4] = *(const float4*)&Bb[(size_t)(n0 + r) * DBC_W + q * 4];
  }
  __syncthreads();

  float acc[2][4][4] = {};
#pragma unroll
  for (int ks = 0; ks < 4; ++ks) {
    int kk = ks * 8;
    uint32_t af[2][4], bfr[4][2];
#pragma unroll
    for (int i = 0; i < 2; i++) {
      int mr = wm * 32 + i * 16;
      af[i][0] = __float_as_uint(As[mr + group    ][kk + tg    ]);
      af[i][1] = __float_as_uint(As[mr + group + 8][kk + tg    ]);
      af[i][2] = __float_as_uint(As[mr + group    ][kk + tg + 4]);
      af[i][3] = __float_as_uint(As[mr + group + 8][kk + tg + 4]);
    }
#pragma unroll
    for (int j = 0; j < 4; j++) {
      int nr = wn * 32 + j * 8;
      bfr[j][0] = __float_as_uint(Bs[nr + group][kk + tg    ]);
      bfr[j][1] = __float_as_uint(Bs[nr + group][kk + tg + 4]);
    }
#pragma unroll
    for (int i = 0; i < 2; i++)
#pragma unroll
      for (int j = 0; j < 4; j++)
        mma_tf32(acc[i][j], af[i], bfr[j]);
  }
  float* ob = outp + (size_t)b * DINNER * SEQ;
#pragma unroll
  for (int i = 0; i < 2; i++) {
    int d0 = m0 + wm * 32 + i * 16 + group;
    float ba = bias[d0], bb2 = bias[d0 + 8];
#pragma unroll
    for (int j = 0; j < 4; j++) {
      int t = n0 + wn * 32 + j * 8 + tg * 2;
      *(float2*)&ob[(size_t)d0 * SEQ + t] =
        make_float2(softplusf(acc[i][j][0] + ba), softplusf(acc[i][j][1] + ba));
      *(float2*)&ob[(size_t)(d0 + 8) * SEQ + t] =
        make_float2(softplusf(acc[i][j][2] + bb2), softplusf(acc[i][j][3] + bb2));
    }
  }
}

// ================= conv + silu + z-silu, transposed to [b,d,t] =================
__global__ void convz_kernel(const float* __restrict__ conv_w, const float* __restrict__ conv_b) {
  __shared__ float sx[67][33];
  __shared__ float sz[64][33];
  int b = blockIdx.z, t0 = blockIdx.x * 64, d0 = blockIdx.y * 32;
  int tid = threadIdx.y * 64 + threadIdx.x;
  for (int i = tid; i < 67*32; i += 256) {
    int r = i >> 5, c = i & 31;
    int t = t0 - 3 + r;
    sx[r][c] = (t >= 0) ? g_xz[(size_t)(b*SEQ + t)*2*DINNER + d0 + c] : 0.f;
  }
  for (int i = tid; i < 64*32; i += 256) {
    int r = i >> 5, c = i & 31;
    sz[r][c] = g_xz[(size_t)(b*SEQ + t0 + r)*2*DINNER + DINNER + d0 + c];
  }
  __syncthreads();
  int tx = threadIdx.x;
#pragma unroll
  for (int i = 0; i < 8; i++) {
    int dl = threadIdx.y * 8 + i;
    int d = d0 + dl;
    float w0 = conv_w[d*4+0], w1 = conv_w[d*4+1], w2 = conv_w[d*4+2], w3 = conv_w[d*4+3];
    float acc = conv_b[d];
    acc += sx[tx+0][dl]*w0 + sx[tx+1][dl]*w1 + sx[tx+2][dl]*w2 + sx[tx+3][dl]*w3;
    size_t o = (size_t)(b*DINNER + d)*SEQ + t0 + tx;
    g_ut[o] = siluf(acc);
    g_zt[o] = siluf(sz[tx][dl]);
  }
}

// ================= selective scan =================
__global__ void scan_kernel(const float* __restrict__ Dw, const float* __restrict__ A_log) {
  int warp = threadIdx.x >> 5, lane = threadIdx.x & 31;
  int g = blockIdx.x * 8 + warp;
  int b = g >> 10, d = g & 1023;
  __shared__ float sBC[32][64];
  __shared__ float sP[8][32][34];
  float An = -__expf(A_log[d*DSTATE + lane]);
  float Dd = Dw[d];
  float h = 0.f;
  const float* ut  = g_ut     + (size_t)(b*DINNER + d)*SEQ;
  const float* dtp = g_deltat + (size_t)(b*DINNER + d)*SEQ;
  const float* ztp = g_zt     + (size_t)(b*DINNER + d)*SEQ;
  float*       ytp = g_yt     + (size_t)(b*DINNER + d)*SEQ;

  for (int t0 = 0; t0 < SEQ; t0 += 32) {
    __syncthreads();
    for (int i = threadIdx.x; i < 32*64; i += 256) {
      int s = i >> 6, c = i & 63;
      sBC[s][c] = g_dbc[(size_t)(b*SEQ + t0 + s)*DBC_W + DSTATE + c];
    }
    __syncthreads();
    float du = ut[t0 + lane];
    float dd = dtp[t0 + lane];
    float sz = ztp[t0 + lane];
#pragma unroll 8
    for (int s = 0; s < 32; s++) {
      float delta_t = __shfl_sync(0xffffffffu, dd, s);
      float u_t     = __shfl_sync(0xffffffffu, du, s);
      float dA = __expf(delta_t * An);
      h = fmaf(dA, h, delta_t * u_t * sBC[s][lane]);
      sP[warp][s][lane] = h * sBC[s][32 + lane];
    }
    __syncwarp();
    float y = du * Dd;
#pragma unroll
    for (int i = 0; i < 32; i++) {
      int c = (lane + i) & 31;
      y += sP[warp][lane][c];
    }
    ytp[t0 + lane] = y * sz;
  }
}

// ================= layernorm =================
__global__ void ln_kernel(const float* __restrict__ lnw, const float* __restrict__ lnb) {
  int row = blockIdx.x;
  const float* y = g_y2 + (size_t)row * DMODEL;
  float*       o = g_yn + (size_t)row * DMODEL;
  int tid = threadIdx.x;
  int lane = tid & 31, wid = tid >> 5;
  float v[4], s = 0.f, s2 = 0.f;
#pragma unroll
  for (int i = 0; i < 4; i++) {
    float x = y[tid + i*128];
    v[i] = x; s += x; s2 += x*x;
  }
#pragma unroll
  for (int off = 16; off >= 1; off >>= 1) {
    s  += __shfl_xor_sync(0xffffffffu, s, off);
    s2 += __shfl_xor_sync(0xffffffffu, s2, off);
  }
  __shared__ float sh[10];
  if (lane == 0) { sh[wid] = s; sh[4 + wid] = s2; }
  __syncthreads();
  if (tid == 0) {
    float ts = sh[0] + sh[1] + sh[2] + sh[3];
    float ts2 = sh[4] + sh[5] + sh[6] + sh[7];
    float mu = ts * (1.f/DMODEL);
    float var = ts2 * (1.f/DMODEL) - mu*mu;
    sh[8] = mu;
    sh[9] = rsqrtf(var + 1e-5f);
  }
  __syncthreads();
  float mu = sh[8], inv = sh[9];
#pragma unroll
  for (int i = 0; i < 4; i++) {
    int c = tid + i*128;
    o[c] = (v[i] - mu) * inv * lnw[c] + lnb[c];
  }
}

// ================= launch =================
extern "C" void kernel_launch(void* const* d_in, const int* in_sizes, int n_in,
                              void* d_out, int out_size) {
  const float* tokens     = (const float*)d_in[0];
  const float* in_proj_w  = (const float*)d_in[1];
  const float* conv_w     = (const float*)d_in[2];
  const float* conv_b     = (const float*)d_in[3];
  const float* x_proj_w   = (const float*)d_in[4];
  const float* dt_proj_w  = (const float*)d_in[5];
  const float* dt_proj_b  = (const float*)d_in[6];
  const float* A_log      = (const float*)d_in[7];
  const float* Dw         = (const float*)d_in[8];
  const float* out_proj_w = (const float*)d_in[9];
  const float* ln_w       = (const float*)d_in[10];
  const float* ln_b       = (const float*)d_in[11];
  const float* lin_w      = (const float*)d_in[12];
  const float* lin_b      = (const float*)d_in[13];
  float* out = (float*)d_out;

  float *p_xz, *p_ut, *p_dbcp, *p_dbc, *p_deltat, *p_yt, *p_y2, *p_yn;
  cudaGetSymbolAddress((void**)&p_xz,     g_xz);
  cudaGetSymbolAddress((void**)&p_ut,     g_ut);
  cudaGetSymbolAddress((void**)&p_dbcp,   g_dbcp);
  cudaGetSymbolAddress((void**)&p_dbc,    g_dbc);
  cudaGetSymbolAddress((void**)&p_deltat, g_deltat);
  cudaGetSymbolAddress((void**)&p_yt,     g_yt);
  cudaGetSymbolAddress((void**)&p_y2,     g_y2);
  cudaGetSymbolAddress((void**)&p_yn,     g_yn);

  cudaFuncSetAttribute(gemm_nt, cudaFuncAttributeMaxDynamicSharedMemorySize, NT_SMEM3);
  cudaFuncSetAttribute(gemm_tn<128,4>, cudaFuncAttributeMaxDynamicSharedMemorySize, TN_SMEM3_128);
  cudaFuncSetAttribute(gemm_tn<64,2>,  cudaFuncAttributeMaxDynamicSharedMemorySize, TN_SMEM3_64);

  // 1. xz = perm(tokens) @ in_proj_w^T
  gemm_nt<<<dim3(2*DINNER/128, NROWS/128), 256, NT_SMEM3>>>(tokens, in_proj_w, p_xz,
                                                            NROWS, 2*DINNER, DMODEL,
                                                            1, 0, nullptr, nullptr);
  // 2. conv+silu -> ut ; silu(z) -> zt
  convz_kernel<<<dim3(SEQ/64, DINNER/32, BATCH), dim3(64,4)>>>(conv_w, conv_b);
  // 3. dbc partials (split-K=4)
  gemm_tn<128,4><<<dim3(1, SEQ/128, BATCH*XSPLIT), 256, TN_SMEM3_128>>>(
      p_ut, x_proj_w, p_dbcp, SEQ, DBC_W, DINNER, SEQ, DINNER*SEQ, SEQ*DBC_W, XSPLIT);
  // 3b. reduce partials
  reduce_dbc<<<(BATCH*SEQ*DBC_W/4 + 255)/256, 256>>>();
  // 4. delta
  delta_mma<<<dim3(SEQ/64, DINNER/128, BATCH), 256>>>(dt_proj_w, p_dbc, dt_proj_b, p_deltat);
  // 5. scan
  scan_kernel<<<NROWS/8, 256>>>(Dw, A_log);
  // 6. y2 = y @ out_proj_w^T
  gemm_tn<64,2><<<dim3(DMODEL/128, SEQ/64, BATCH), 256, TN_SMEM3_64>>>(
      p_yt, out_proj_w, p_y2, SEQ, DMODEL, DINNER, SEQ, DINNER*SEQ, SEQ*DMODEL, 1);
  // 7. layernorm
  ln_kernel<<<NROWS, 128>>>(ln_w, ln_b);
  // 8. out = gelu(yn @ lin_w^T + lin_b) + residual
  gemm_nt<<<dim3(DMODEL/128, NROWS/128), 256, NT_SMEM3>>>(p_yn, lin_w, out,
                                                          NROWS, DMODEL, DMODEL,
                                                          0, 1, lin_b, tokens);
}